// round 3
// baseline (speedup 1.0000x reference)
#include <cuda_runtime.h>
#include <math.h>

// Problem constants
#define Bsz  8
#define Cch  256
#define Hh   56
#define Ww   56
#define Lrows (Bsz * Hh * Ww)   // 25088
#define Dd    (Cch * 9)         // 2304

// Scratch (allocation-free rule: __device__ globals)
// g_t : unfolded patches, COLUMN-major [L x D]  -> g_t[d*L + l]
//       (after kernel 3 it holds t*s in place)
// g_h1: hidden relu activations, COLUMN-major [L x C] -> g_h1[c*L + l]
__device__ float g_t [Lrows * Dd];   // ~231 MB
__device__ float g_h1[Lrows * Cch];  // ~25.7 MB

// ---------------------------------------------------------------------------
// Kernel 1: unfold3x3 (pad=1). One block per (b, c, i); threads over j.
// Writes column-major: coalesced along l (=j fastest).
// ---------------------------------------------------------------------------
__global__ void unfold_kernel(const float* __restrict__ x) {
    int bci = blockIdx.x;
    int i  = bci % Hh;
    int bc = bci / Hh;
    int c  = bc % Cch;
    int b  = bc / Cch;
    int j  = threadIdx.x;
    if (j >= Ww) return;

    const float* xc = x + (size_t)(b * Cch + c) * (Hh * Ww);
    int l = b * (Hh * Ww) + i * Ww + j;
    size_t base = (size_t)(c * 9) * Lrows + l;

    #pragma unroll
    for (int ki = 0; ki < 3; ki++) {
        int ii = i + ki - 1;
        #pragma unroll
        for (int kj = 0; kj < 3; kj++) {
            int jj = j + kj - 1;
            float v = 0.f;
            if (ii >= 0 && ii < Hh && jj >= 0 && jj < Ww)
                v = xc[ii * Ww + jj];
            g_t[base + (size_t)(ki * 3 + kj) * Lrows] = v;
        }
    }
}

// ---------------------------------------------------------------------------
// SGEMM: C[M,N] = act(A[M,K] * B[K,N] + bias)
//   A: column-major (lda = M)  -- g_t (ASRC=0) or g_h1 (ASRC=1)
//   B: row-major    (ldb = N)  -- weight matrix from inputs
// Block tile: 128 x BN_ x 8, 256 threads, microtile TM=8 x TN_.
// EPI: 0 = relu,   store col-major to g_h1
//      1 = sigmoid, multiply g_t elementwise, store back to g_t (in place)
//      2 = bias only, store row-major to Cout (final output)
// ---------------------------------------------------------------------------
template<int ASRC, int BN_, int TN_, int EPI>
__global__ __launch_bounds__(256) void gemm_kernel(
    const float* __restrict__ Bmat,
    const float* __restrict__ bias,
    float* __restrict__ Cout,
    int M, int N, int Kd)
{
    constexpr int BM = 128, BK = 8, TM = 8;
    __shared__ float As[BK][BM];
    __shared__ float Bs[BK][BN_];

    const float* __restrict__ A = (ASRC == 0) ? g_t : g_h1;

    int tid = threadIdx.x;
    int bm  = blockIdx.y * BM;
    int bn  = blockIdx.x * BN_;

    // A-tile load map: 128x8 = 256 float4 along m
    int a_k = tid >> 5;            // 0..7
    int a_m = (tid & 31) << 2;     // 0..124
    // B-tile load map: 8 x BN_ floats = (BN_*2) float4 along n
    constexpr int BROW4 = BN_ / 4;
    int  b_k   = tid / BROW4;
    int  b_n   = (tid % BROW4) << 2;
    bool bload = (tid < BK * BROW4);

    // microtile position
    int tidm = tid & 15;
    int tidn = tid >> 4;
    int tm0  = tidm * TM;
    int tn0  = tidn * TN_;

    float acc[TM][TN_];
    #pragma unroll
    for (int m = 0; m < TM; m++)
        #pragma unroll
        for (int n = 0; n < TN_; n++)
            acc[m][n] = 0.f;

    for (int k0 = 0; k0 < Kd; k0 += BK) {
        *(float4*)&As[a_k][a_m] =
            *(const float4*)&A[(size_t)(k0 + a_k) * M + bm + a_m];
        if (bload)
            *(float4*)&Bs[b_k][b_n] =
                *(const float4*)&Bmat[(size_t)(k0 + b_k) * N + bn + b_n];
        __syncthreads();

        #pragma unroll
        for (int kk = 0; kk < BK; kk++) {
            float af[TM], bf[TN_];
            #pragma unroll
            for (int m = 0; m < TM; m++) af[m] = As[kk][tm0 + m];
            #pragma unroll
            for (int n = 0; n < TN_; n++) bf[n] = Bs[kk][tn0 + n];
            #pragma unroll
            for (int m = 0; m < TM; m++)
                #pragma unroll
                for (int n = 0; n < TN_; n++)
                    acc[m][n] = fmaf(af[m], bf[n], acc[m][n]);
        }
        __syncthreads();
    }

    if (EPI == 2) {
        // row-major output: out[l, n]
        #pragma unroll
        for (int m = 0; m < TM; m++) {
            size_t row = (size_t)(bm + tm0 + m) * N + bn + tn0;
            #pragma unroll
            for (int n = 0; n < TN_; n += 4) {
                float4 v;
                v.x = acc[m][n + 0] + bias[bn + tn0 + n + 0];
                v.y = acc[m][n + 1] + bias[bn + tn0 + n + 1];
                v.z = acc[m][n + 2] + bias[bn + tn0 + n + 2];
                v.w = acc[m][n + 3] + bias[bn + tn0 + n + 3];
                *(float4*)&Cout[row + n] = v;
            }
        }
    } else {
        // column-major stores along m
        #pragma unroll
        for (int n = 0; n < TN_; n++) {
            float bv = bias[bn + tn0 + n];
            size_t col = (size_t)(bn + tn0 + n) * M + bm + tm0;
            #pragma unroll
            for (int m = 0; m < TM; m += 4) {
                if (EPI == 0) {
                    float4 v;
                    v.x = fmaxf(acc[m + 0][n] + bv, 0.f);
                    v.y = fmaxf(acc[m + 1][n] + bv, 0.f);
                    v.z = fmaxf(acc[m + 2][n] + bv, 0.f);
                    v.w = fmaxf(acc[m + 3][n] + bv, 0.f);
                    *(float4*)&g_h1[col + m] = v;
                } else {
                    // ts = t * sigmoid(acc + b) = t / (1 + exp(-(acc+b)))
                    float4 tv = *(const float4*)&g_t[col + m];
                    float4 v;
                    v.x = tv.x / (1.f + expf(-(acc[m + 0][n] + bv)));
                    v.y = tv.y / (1.f + expf(-(acc[m + 1][n] + bv)));
                    v.z = tv.z / (1.f + expf(-(acc[m + 2][n] + bv)));
                    v.w = tv.w / (1.f + expf(-(acc[m + 3][n] + bv)));
                    *(float4*)&g_t[col + m] = v;
                }
            }
        }
    }
}

// ---------------------------------------------------------------------------
// Launch: unfold -> GEMM1(relu) -> GEMM2(sigmoid * t, in place) -> GEMM3(out)
// All on the default stream; graph-capturable (kernel launches only).
// ---------------------------------------------------------------------------
extern "C" void kernel_launch(void* const* d_in, const int* in_sizes, int n_in,
                              void* d_out, int out_size)
{
    const float* x  = (const float*)d_in[0];
    const float* W1 = (const float*)d_in[1];
    const float* b1 = (const float*)d_in[2];
    const float* W2 = (const float*)d_in[3];
    const float* b2 = (const float*)d_in[4];
    const float* W3 = (const float*)d_in[5];
    const float* b3 = (const float*)d_in[6];
    float* out = (float*)d_out;
    (void)in_sizes; (void)n_in; (void)out_size;

    // K1: unfold x -> g_t (col-major [L x D])
    unfold_kernel<<<Bsz * Cch * Hh, 64>>>(x);

    // K2: h1 = relu(t @ W1 + b1)   M=25088, N=256, K=2304
    gemm_kernel<0, 64, 4, 0><<<dim3(Cch / 64, Lrows / 128), 256>>>(
        W1, b1, nullptr, Lrows, Cch, Dd);

    // K3: g_t = g_t * sigmoid(h1 @ W2 + b2)   M=25088, N=2304, K=256
    gemm_kernel<1, 128, 8, 1><<<dim3(Dd / 128, Lrows / 128), 256>>>(
        W2, b2, nullptr, Lrows, Dd, Cch);

    // K4: out = ts @ W3 + b3   M=25088, N=256, K=2304, row-major output
    gemm_kernel<0, 64, 4, 2><<<dim3(Cch / 64, Lrows / 128), 256>>>(
        W3, b3, out, Lrows, Cch, Dd);
}

// round 6
// speedup vs baseline: 1.1916x; 1.1916x over previous
#include <cuda_runtime.h>
#include <math.h>

// Problem constants
#define Bsz  8
#define Cch  256
#define Hh   56
#define Ww   56
#define Lrows (Bsz * Hh * Ww)   // 25088
#define Dd    (Cch * 9)         // 2304

// Scratch (__device__ globals: allocation-free rule)
// g_t : unfolded patches, COLUMN-major [L x D]  -> g_t[d*L + l]
//       (after GEMM2 it holds t*s in place)
// g_h1: hidden relu activations, COLUMN-major [L x C]
__device__ float g_t [Lrows * Dd];   // ~231 MB
__device__ float g_h1[Lrows * Cch];  // ~25.7 MB

// ---------------------------------------------------------------------------
// f32x2 helpers (packed dual-FMA, SASS FFMA2 — only reachable via PTX)
// ---------------------------------------------------------------------------
__device__ __forceinline__ unsigned long long ffma2(
    unsigned long long a, unsigned long long b, unsigned long long c) {
    unsigned long long d;
    asm("fma.rn.f32x2 %0, %1, %2, %3;" : "=l"(d) : "l"(a), "l"(b), "l"(c));
    return d;
}
__device__ __forceinline__ unsigned long long bcast2(float v) {
    unsigned long long d;
    asm("mov.b64 %0, {%1, %1};" : "=l"(d) : "f"(v));
    return d;
}
__device__ __forceinline__ float2 u2f(unsigned long long v) {
    float2 r;
    asm("mov.b64 {%0, %1}, %2;" : "=f"(r.x), "=f"(r.y) : "l"(v));
    return r;
}

// ---------------------------------------------------------------------------
// Kernel 1: unfold3x3 (pad=1). One block per (b, c, i); threads over j.
// Writes column-major: coalesced along l (=j fastest).
// ---------------------------------------------------------------------------
__global__ void unfold_kernel(const float* __restrict__ x) {
    int bci = blockIdx.x;
    int i  = bci % Hh;
    int bc = bci / Hh;
    int c  = bc % Cch;
    int b  = bc / Cch;
    int j  = threadIdx.x;
    if (j >= Ww) return;

    const float* xc = x + (size_t)(b * Cch + c) * (Hh * Ww);
    int l = b * (Hh * Ww) + i * Ww + j;
    size_t base = (size_t)(c * 9) * Lrows + l;

    #pragma unroll
    for (int ki = 0; ki < 3; ki++) {
        int ii = i + ki - 1;
        #pragma unroll
        for (int kj = 0; kj < 3; kj++) {
            int jj = j + kj - 1;
            float v = 0.f;
            if (ii >= 0 && ii < Hh && jj >= 0 && jj < Ww)
                v = xc[ii * Ww + jj];
            g_t[base + (size_t)(ki * 3 + kj) * Lrows] = v;
        }
    }
}

// ---------------------------------------------------------------------------
// SGEMM: C[M,N] = act(A[M,K] * B[K,N] + bias)
//   A col-major (lda=M): g_t (ASRC=0) or g_h1 (ASRC=1)
//   B row-major (ldb=N): weight from inputs
// Tile: 128 x 128 x 16, 512 threads, microtile 8x4, packed-f32x2 FMA,
// double-buffered smem (one __syncthreads per 16 k-steps).
// EPI: 0 relu -> g_h1 (col-major), 1 t*sigmoid -> g_t in place (col-major),
//      2 bias -> Cout (row-major)
// ---------------------------------------------------------------------------
template<int ASRC, int EPI>
__global__ __launch_bounds__(512) void gemm_kernel(
    const float* __restrict__ Bmat,
    const float* __restrict__ bias,
    float* __restrict__ Cout,
    int M, int N, int Kd)
{
    constexpr int BM = 128, BN = 128, BK = 16;
    __shared__ float As[2][BK][BM];
    __shared__ float Bs[2][BK][BN];

    const float* __restrict__ A = (ASRC == 0) ? g_t : g_h1;

    int tid = threadIdx.x;
    int bm  = blockIdx.y * BM;
    int bn  = blockIdx.x * BN;

    // global->smem load maps (1 float4 each per thread)
    int a_k = tid >> 5;               // 0..15
    int a_m = (tid & 31) << 2;        // 0..124
    int b_k = tid >> 5;               // 0..15
    int b_n = (tid & 31) << 2;        // 0..124

    // microtile: 16 m-threads x 32 n-threads; m in two chunks (+0, +64)
    int tidm   = tid & 15;
    int tidn   = tid >> 4;            // 0..31
    int m_base = tidm * 4;            // 0..60
    int n_base = tidn * 4;            // 0..124

    // acc pairs along m: mi 0:(m+0,m+1) 1:(m+2,m+3) 2:(m+64,65) 3:(m+66,67)
    unsigned long long acc2[4][4];
    #pragma unroll
    for (int i = 0; i < 4; i++)
        #pragma unroll
        for (int n = 0; n < 4; n++)
            acc2[i][n] = 0ull;

    const int ntiles = Kd / BK;

    // prologue: tile 0 -> smem[0]
    float4 ra = *(const float4*)&A[(size_t)a_k * M + bm + a_m];
    float4 rb = *(const float4*)&Bmat[(size_t)b_k * N + bn + b_n];
    *(float4*)&As[0][a_k][a_m] = ra;
    *(float4*)&Bs[0][b_k][b_n] = rb;
    __syncthreads();

    int buf = 0;
    for (int t = 0; t < ntiles; t++) {
        const bool has_next = (t + 1 < ntiles);
        if (has_next) {
            int k0 = (t + 1) * BK;
            ra = *(const float4*)&A[(size_t)(k0 + a_k) * M + bm + a_m];
            rb = *(const float4*)&Bmat[(size_t)(k0 + b_k) * N + bn + b_n];
        }

        #pragma unroll
        for (int kk = 0; kk < BK; kk++) {
            ulonglong2 aL = *(const ulonglong2*)&As[buf][kk][m_base];
            ulonglong2 aH = *(const ulonglong2*)&As[buf][kk][m_base + 64];
            float4 bv = *(const float4*)&Bs[buf][kk][n_base];
            unsigned long long bb0 = bcast2(bv.x);
            unsigned long long bb1 = bcast2(bv.y);
            unsigned long long bb2 = bcast2(bv.z);
            unsigned long long bb3 = bcast2(bv.w);
            acc2[0][0] = ffma2(aL.x, bb0, acc2[0][0]);
            acc2[0][1] = ffma2(aL.x, bb1, acc2[0][1]);
            acc2[0][2] = ffma2(aL.x, bb2, acc2[0][2]);
            acc2[0][3] = ffma2(aL.x, bb3, acc2[0][3]);
            acc2[1][0] = ffma2(aL.y, bb0, acc2[1][0]);
            acc2[1][1] = ffma2(aL.y, bb1, acc2[1][1]);
            acc2[1][2] = ffma2(aL.y, bb2, acc2[1][2]);
            acc2[1][3] = ffma2(aL.y, bb3, acc2[1][3]);
            acc2[2][0] = ffma2(aH.x, bb0, acc2[2][0]);
            acc2[2][1] = ffma2(aH.x, bb1, acc2[2][1]);
            acc2[2][2] = ffma2(aH.x, bb2, acc2[2][2]);
            acc2[2][3] = ffma2(aH.x, bb3, acc2[2][3]);
            acc2[3][0] = ffma2(aH.y, bb0, acc2[3][0]);
            acc2[3][1] = ffma2(aH.y, bb1, acc2[3][1]);
            acc2[3][2] = ffma2(aH.y, bb2, acc2[3][2]);
            acc2[3][3] = ffma2(aH.y, bb3, acc2[3][3]);
        }

        if (has_next) {
            *(float4*)&As[buf ^ 1][a_k][a_m] = ra;
            *(float4*)&Bs[buf ^ 1][b_k][b_n] = rb;
            __syncthreads();
            buf ^= 1;
        }
    }

    if (EPI == 2) {
        // row-major out[l, n]
        float av[8][4];
        #pragma unroll
        for (int n = 0; n < 4; n++) {
            float2 p;
            p = u2f(acc2[0][n]); av[0][n] = p.x; av[1][n] = p.y;
            p = u2f(acc2[1][n]); av[2][n] = p.x; av[3][n] = p.y;
            p = u2f(acc2[2][n]); av[4][n] = p.x; av[5][n] = p.y;
            p = u2f(acc2[3][n]); av[6][n] = p.x; av[7][n] = p.y;
        }
        float4 bv4 = *(const float4*)&bias[bn + n_base];
        #pragma unroll
        for (int r = 0; r < 8; r++) {
            int m = bm + m_base + ((r < 4) ? r : (60 + r));  // +64 chunk
            float4 v;
            v.x = av[r][0] + bv4.x;
            v.y = av[r][1] + bv4.y;
            v.z = av[r][2] + bv4.z;
            v.w = av[r][3] + bv4.w;
            *(float4*)&Cout[(size_t)m * N + bn + n_base] = v;
        }
    } else {
        #pragma unroll
        for (int n = 0; n < 4; n++) {
            float bv = bias[bn + n_base + n];
            size_t col = (size_t)(bn + n_base + n) * M + bm;
            float2 p0 = u2f(acc2[0][n]);
            float2 p1 = u2f(acc2[1][n]);
            float2 p2 = u2f(acc2[2][n]);
            float2 p3 = u2f(acc2[3][n]);
            if (EPI == 0) {
                float4 v0, v1;
                v0.x = fmaxf(p0.x + bv, 0.f);
                v0.y = fmaxf(p0.y + bv, 0.f);
                v0.z = fmaxf(p1.x + bv, 0.f);
                v0.w = fmaxf(p1.y + bv, 0.f);
                v1.x = fmaxf(p2.x + bv, 0.f);
                v1.y = fmaxf(p2.y + bv, 0.f);
                v1.z = fmaxf(p3.x + bv, 0.f);
                v1.w = fmaxf(p3.y + bv, 0.f);
                *(float4*)&g_h1[col + m_base]      = v0;
                *(float4*)&g_h1[col + m_base + 64] = v1;
            } else {
                // t * sigmoid(z) = t / (1 + exp(-z))
                float4 t0 = *(const float4*)&g_t[col + m_base];
                float4 t1 = *(const float4*)&g_t[col + m_base + 64];
                float4 v0, v1;
                v0.x = __fdividef(t0.x, 1.f + __expf(-(p0.x + bv)));
                v0.y = __fdividef(t0.y, 1.f + __expf(-(p0.y + bv)));
                v0.z = __fdividef(t0.z, 1.f + __expf(-(p1.x + bv)));
                v0.w = __fdividef(t0.w, 1.f + __expf(-(p1.y + bv)));
                v1.x = __fdividef(t1.x, 1.f + __expf(-(p2.x + bv)));
                v1.y = __fdividef(t1.y, 1.f + __expf(-(p2.y + bv)));
                v1.z = __fdividef(t1.z, 1.f + __expf(-(p3.x + bv)));
                v1.w = __fdividef(t1.w, 1.f + __expf(-(p3.y + bv)));
                *(float4*)&g_t[col + m_base]      = v0;
                *(float4*)&g_t[col + m_base + 64] = v1;
            }
        }
    }
}

// ---------------------------------------------------------------------------
// Launch: unfold -> GEMM1(relu) -> GEMM2(sigmoid*t in place) -> GEMM3(out)
// ---------------------------------------------------------------------------
extern "C" void kernel_launch(void* const* d_in, const int* in_sizes, int n_in,
                              void* d_out, int out_size)
{
    const float* x  = (const float*)d_in[0];
    const float* W1 = (const float*)d_in[1];
    const float* b1 = (const float*)d_in[2];
    const float* W2 = (const float*)d_in[3];
    const float* b2 = (const float*)d_in[4];
    const float* W3 = (const float*)d_in[5];
    const float* b3 = (const float*)d_in[6];
    float* out = (float*)d_out;
    (void)in_sizes; (void)n_in; (void)out_size;

    // K1: unfold x -> g_t (col-major [L x D])
    unfold_kernel<<<Bsz * Cch * Hh, 64>>>(x);

    // K2: h1 = relu(t @ W1 + b1)   M=25088, N=256, K=2304
    gemm_kernel<0, 0><<<dim3(Cch / 128, Lrows / 128), 512>>>(
        W1, b1, nullptr, Lrows, Cch, Dd);

    // K3: g_t = g_t * sigmoid(h1 @ W2 + b2)   M=25088, N=2304, K=256
    gemm_kernel<1, 1><<<dim3(Dd / 128, Lrows / 128), 512>>>(
        W2, b2, nullptr, Lrows, Dd, Cch);

    // K4: out = ts @ W3 + b3   M=25088, N=256, K=2304, row-major out
    gemm_kernel<0, 2><<<dim3(Cch / 128, Lrows / 128), 512>>>(
        W3, b3, out, Lrows, Cch, Dd);
}

// round 8
// speedup vs baseline: 2.3088x; 1.9375x over previous
#include <cuda_runtime.h>
#include <cuda_bf16.h>
#include <math.h>

// ---------------------------------------------------------------------------
// Problem constants
// ---------------------------------------------------------------------------
#define Bsz  8
#define Cch  256
#define Hh   56
#define Ww   56
#define Lrows (Bsz * Hh * Ww)   // 25088
#define Dd    (Cch * 9)         // 2304

// ---------------------------------------------------------------------------
// Global scratch (__device__ arrays: allocation-free rule)
// ---------------------------------------------------------------------------
__device__ float g_t [(size_t)Lrows * Dd];   // unfolded t, ROW-major [L][2304]; after GEMM2 holds t*s
__device__ float g_h1[(size_t)Lrows * Cch];  // relu hidden, ROW-major [L][256]
// weights transposed to K-major [N][K], split into bf16 hi/lo
__device__ __nv_bfloat16 g_W1T_hi[Cch * Dd], g_W1T_lo[Cch * Dd];
__device__ __nv_bfloat16 g_W2T_hi[Dd * Cch], g_W2T_lo[Dd * Cch];
__device__ __nv_bfloat16 g_W3T_hi[Cch * Dd], g_W3T_lo[Cch * Dd];

// ---------------------------------------------------------------------------
// PTX helpers (all sm_80-era: compile at plain sm_103 target)
// ---------------------------------------------------------------------------
__device__ __forceinline__ unsigned smem_u32(const void* p) {
    unsigned a;
    asm("{ .reg .u64 t; cvta.to.shared.u64 t, %1; cvt.u32.u64 %0, t; }" : "=r"(a) : "l"(p));
    return a;
}
__device__ __forceinline__ void ldsm4(unsigned addr, unsigned r[4]) {
    asm volatile("ldmatrix.sync.aligned.m8n8.x4.shared.b16 {%0,%1,%2,%3}, [%4];"
        : "=r"(r[0]), "=r"(r[1]), "=r"(r[2]), "=r"(r[3]) : "r"(addr));
}
__device__ __forceinline__ void mma16816(float d[4], const unsigned a[4],
                                         unsigned b0, unsigned b1) {
    asm volatile("mma.sync.aligned.m16n8k16.row.col.f32.bf16.bf16.f32 "
        "{%0,%1,%2,%3}, {%4,%5,%6,%7}, {%8,%9}, {%0,%1,%2,%3};"
        : "+f"(d[0]), "+f"(d[1]), "+f"(d[2]), "+f"(d[3])
        : "r"(a[0]), "r"(a[1]), "r"(a[2]), "r"(a[3]), "r"(b0), "r"(b1));
}
#define STS128V(addr, v) \
    asm volatile("st.shared.v4.b32 [%0], {%1,%2,%3,%4};" \
                 :: "r"(addr), "r"((v).x), "r"((v).y), "r"((v).z), "r"((v).w) : "memory")

// bf16 hi/lo split of a float pair, packed into one b32 each (low half = first elem)
__device__ __forceinline__ void split2(float x, float y, unsigned& h, unsigned& l) {
    __nv_bfloat16 hx = __float2bfloat16(x);
    __nv_bfloat16 hy = __float2bfloat16(y);
    float rx = x - __bfloat162float(hx);
    float ry = y - __bfloat162float(hy);
    __nv_bfloat162 hp; hp.x = hx; hp.y = hy;
    __nv_bfloat162 lp; lp.x = __float2bfloat16(rx); lp.y = __float2bfloat16(ry);
    h = *(unsigned*)&hp;
    l = *(unsigned*)&lp;
}

// ---------------------------------------------------------------------------
// Kernel: transpose + bf16-split weights  W[K][N] -> T_hi/T_lo [N][K]
// ---------------------------------------------------------------------------
__global__ void transpose_split(const float* __restrict__ W,
                                __nv_bfloat16* __restrict__ Thi,
                                __nv_bfloat16* __restrict__ Tlo,
                                int K, int N)
{
    __shared__ float tile[32][33];
    int n0 = blockIdx.x * 32;
    int k0 = blockIdx.y * 32;
    int tx = threadIdx.x, ty = threadIdx.y;
    #pragma unroll
    for (int r = 0; r < 32; r += 8)
        tile[ty + r][tx] = W[(size_t)(k0 + ty + r) * N + n0 + tx];
    __syncthreads();
    #pragma unroll
    for (int r = 0; r < 32; r += 8) {
        int n = n0 + ty + r;
        int k = k0 + tx;
        float v = tile[tx][ty + r];
        __nv_bfloat16 h = __float2bfloat16(v);
        Thi[(size_t)n * K + k] = h;
        Tlo[(size_t)n * K + k] = __float2bfloat16(v - __bfloat162float(h));
    }
}

// ---------------------------------------------------------------------------
// Kernel: unfold3x3 (pad=1) -> g_t ROW-major [L][2304] (d = c*9 + ki*3 + kj).
// Block per (b, i): stage 3 input rows (all channels) in smem, then write
// 56 coalesced 2304-wide output rows.
// ---------------------------------------------------------------------------
__global__ void unfold_kernel(const float* __restrict__ x) {
    extern __shared__ float xs[];            // [3][256][56]
    const int RSZ = Cch * Ww;                // 14336
    int b = blockIdx.x / Hh;
    int i = blockIdx.x % Hh;
    int tid = threadIdx.x;                   // 256

    for (int idx = tid; idx < 3 * RSZ; idx += 256) {
        int ki  = idx / RSZ;
        int rem = idx - ki * RSZ;
        int c = rem / Ww;
        int j = rem - c * Ww;
        int ii = i + ki - 1;
        float v = 0.f;
        if (ii >= 0 && ii < Hh)
            v = x[(size_t)(b * Cch + c) * (Hh * Ww) + ii * Ww + j];
        xs[idx] = v;
    }
    __syncthreads();

    int soff[9], kjv[9];
    #pragma unroll
    for (int it = 0; it < 9; it++) {
        int d = tid + it * 256;
        int c = d / 9;
        int r = d - c * 9;
        int ki = r / 3;
        kjv[it]  = r - ki * 3;
        soff[it] = ki * RSZ + c * Ww;
    }

    for (int j = 0; j < Ww; j++) {
        size_t lbase = ((size_t)(b * Hh + i) * Ww + j) * Dd;
        #pragma unroll
        for (int it = 0; it < 9; it++) {
            int jj = j + kjv[it] - 1;
            float v = (jj >= 0 && jj < Ww) ? xs[soff[it] + jj] : 0.f;
            g_t[lbase + tid + it * 256] = v;
        }
    }
}

// ---------------------------------------------------------------------------
// HMMA GEMM: C[M=25088, N] = act(A[M,K] @ B^T + bias)
//   A fp32 row-major global (g_t K=2304 / g_h1 K=256), hi/lo split on stage
//   B pre-split bf16 K-major [N][K]
//   3-term split accumulated in fp32: Ah*Bh + Ah*Bl + Al*Bh
// Tile BM=128 x BN=128 x BK=32, 256 threads (8 warps, 4m x 2n, warp 32x64),
// smem rows padded to 80B (conflict-free ldmatrix), double-buffered,
// one __syncthreads per k-iter with register prefetch.
// EPI: 0 relu->g_h1, 1 t*sigmoid->g_t in place, 2 bias->Cout
// ---------------------------------------------------------------------------
template<int EPI, int ASRC>
__global__ __launch_bounds__(256, 1) void gemm_mma(
    const __nv_bfloat16* __restrict__ BT_hi,
    const __nv_bfloat16* __restrict__ BT_lo,
    const float* __restrict__ bias,
    float* __restrict__ Cout)
{
    constexpr int BM = 128, BN = 128, BK = 32;
    constexpr int KD = (ASRC == 0) ? Dd : Cch;   // 2304 or 256
    constexpr int NT = KD / BK;                   // 72 or 8
    constexpr int NOUT = (EPI == 1) ? Dd : Cch;   // output row stride
    constexpr unsigned ROWB = 80;                 // padded smem row bytes
    constexpr unsigned MATB = 128 * ROWB;         // 10240 B per matrix
    constexpr unsigned OFF_AH = 0, OFF_AL = MATB, OFF_BH = 2 * MATB, OFF_BL = 3 * MATB;
    constexpr unsigned STAGE = 4 * MATB;          // 40960
    constexpr unsigned OFF_BIAS = 2 * STAGE;      // 81920

    extern __shared__ char smem[];
    const unsigned sb = smem_u32(smem);
    float* sm_bias = (float*)(smem + OFF_BIAS);

    const float* __restrict__ A = (ASRC == 0) ? g_t : g_h1;

    const int tid = threadIdx.x;
    const int wid = tid >> 5;
    const int lid = tid & 31;
    const int wm  = wid & 3;          // 0..3 -> m offset wm*32
    const int wn  = wid >> 2;         // 0..1 -> n offset wn*64
    const int bm  = blockIdx.y * BM;
    const int bn  = blockIdx.x * BN;

    // staging map: thread -> (row = tid>>1, half = tid&1), 16 elems of k
    const int srow  = tid >> 1;
    const int shalf = tid & 1;
    const unsigned sts_off = (unsigned)srow * ROWB + (unsigned)shalf * 32;

    // ldmatrix per-lane offsets
    const unsigned a_lane = (unsigned)((((lid >> 3) & 1) * 8 + (lid & 7))) * ROWB
                          + (unsigned)(lid >> 4) * 16;
    const unsigned b_lane = (unsigned)((((lid >> 4) & 1) * 8 + (lid & 7))) * ROWB
                          + (unsigned)((lid >> 3) & 1) * 16;

    if (tid < BN) sm_bias[tid] = bias[bn + tid];

    float acc[2][8][4];
    #pragma unroll
    for (int i = 0; i < 2; i++)
        #pragma unroll
        for (int j = 0; j < 8; j++)
            #pragma unroll
            for (int v = 0; v < 4; v++)
                acc[i][j][v] = 0.f;

    // ---- prologue: stage tile 0 ----
    {
        const float* ap = A + (size_t)(bm + srow) * KD + shalf * 16;
        float4 f0 = *(const float4*)(ap + 0);
        float4 f1 = *(const float4*)(ap + 4);
        float4 f2 = *(const float4*)(ap + 8);
        float4 f3 = *(const float4*)(ap + 12);
        uint4 h0, l0, h1, l1;
        split2(f0.x, f0.y, h0.x, l0.x); split2(f0.z, f0.w, h0.y, l0.y);
        split2(f1.x, f1.y, h0.z, l0.z); split2(f1.z, f1.w, h0.w, l0.w);
        split2(f2.x, f2.y, h1.x, l1.x); split2(f2.z, f2.w, h1.y, l1.y);
        split2(f3.x, f3.y, h1.z, l1.z); split2(f3.z, f3.w, h1.w, l1.w);
        STS128V(sb + OFF_AH + sts_off,      h0);
        STS128V(sb + OFF_AH + sts_off + 16, h1);
        STS128V(sb + OFF_AL + sts_off,      l0);
        STS128V(sb + OFF_AL + sts_off + 16, l1);

        const __nv_bfloat16* bh = BT_hi + (size_t)(bn + srow) * KD + shalf * 16;
        const __nv_bfloat16* bl = BT_lo + (size_t)(bn + srow) * KD + shalf * 16;
        uint4 vh0 = *(const uint4*)(bh + 0);
        uint4 vh1 = *(const uint4*)(bh + 8);
        uint4 vl0 = *(const uint4*)(bl + 0);
        uint4 vl1 = *(const uint4*)(bl + 8);
        STS128V(sb + OFF_BH + sts_off,      vh0);
        STS128V(sb + OFF_BH + sts_off + 16, vh1);
        STS128V(sb + OFF_BL + sts_off,      vl0);
        STS128V(sb + OFF_BL + sts_off + 16, vl1);
    }
    __syncthreads();

    for (int t = 0; t < NT; t++) {
        const unsigned so = (t & 1) ? STAGE : 0;
        const bool has_next = (t + 1 < NT);

        // prefetch next tile into registers
        float4 f0, f1, f2, f3;
        uint4  pvh0, pvh1, pvl0, pvl1;
        if (has_next) {
            const int k0 = (t + 1) * BK;
            const float* ap = A + (size_t)(bm + srow) * KD + k0 + shalf * 16;
            f0 = *(const float4*)(ap + 0);
            f1 = *(const float4*)(ap + 4);
            f2 = *(const float4*)(ap + 8);
            f3 = *(const float4*)(ap + 12);
            const __nv_bfloat16* bh = BT_hi + (size_t)(bn + srow) * KD + k0 + shalf * 16;
            const __nv_bfloat16* bl = BT_lo + (size_t)(bn + srow) * KD + k0 + shalf * 16;
            pvh0 = *(const uint4*)(bh + 0);
            pvh1 = *(const uint4*)(bh + 8);
            pvl0 = *(const uint4*)(bl + 0);
            pvl1 = *(const uint4*)(bl + 8);
        }

        // compute on current stage
        #pragma unroll
        for (int ks = 0; ks < 2; ks++) {
            const unsigned kso = (unsigned)ks * 32;
            unsigned Ah[2][4], Al[2][4];
            #pragma unroll
            for (int i = 0; i < 2; i++) {
                unsigned arow = (unsigned)(wm * 32 + i * 16) * ROWB + kso;
                ldsm4(sb + so + OFF_AH + arow + a_lane, Ah[i]);
                ldsm4(sb + so + OFF_AL + arow + a_lane, Al[i]);
            }
            unsigned Bh[4][4], Bl[4][4];
            #pragma unroll
            for (int g = 0; g < 4; g++) {
                unsigned brow = (unsigned)(wn * 64 + g * 16) * ROWB + kso;
                ldsm4(sb + so + OFF_BH + brow + b_lane, Bh[g]);
                ldsm4(sb + so + OFF_BL + brow + b_lane, Bl[g]);
            }
            #pragma unroll
            for (int i = 0; i < 2; i++) {
                #pragma unroll
                for (int g = 0; g < 4; g++) {
                    mma16816(acc[i][2 * g],     Ah[i], Bh[g][0], Bh[g][1]);
                    mma16816(acc[i][2 * g + 1], Ah[i], Bh[g][2], Bh[g][3]);
                    mma16816(acc[i][2 * g],     Ah[i], Bl[g][0], Bl[g][1]);
                    mma16816(acc[i][2 * g + 1], Ah[i], Bl[g][2], Bl[g][3]);
                    mma16816(acc[i][2 * g],     Al[i], Bh[g][0], Bh[g][1]);
                    mma16816(acc[i][2 * g + 1], Al[i], Bh[g][2], Bh[g][3]);
                }
            }
        }

        if (has_next) {
            const unsigned sn = (t & 1) ? 0 : STAGE;
            uint4 h0, l0, h1, l1;
            split2(f0.x, f0.y, h0.x, l0.x); split2(f0.z, f0.w, h0.y, l0.y);
            split2(f1.x, f1.y, h0.z, l0.z); split2(f1.z, f1.w, h0.w, l0.w);
            split2(f2.x, f2.y, h1.x, l1.x); split2(f2.z, f2.w, h1.y, l1.y);
            split2(f3.x, f3.y, h1.z, l1.z); split2(f3.z, f3.w, h1.w, l1.w);
            STS128V(sn + sb + OFF_AH + sts_off,      h0);
            STS128V(sn + sb + OFF_AH + sts_off + 16, h1);
            STS128V(sn + sb + OFF_AL + sts_off,      l0);
            STS128V(sn + sb + OFF_AL + sts_off + 16, l1);
            STS128V(sn + sb + OFF_BH + sts_off,      pvh0);
            STS128V(sn + sb + OFF_BH + sts_off + 16, pvh1);
            STS128V(sn + sb + OFF_BL + sts_off,      pvl0);
            STS128V(sn + sb + OFF_BL + sts_off + 16, pvl1);
            __syncthreads();
        }
    }

    // ---- epilogue: acc lane mapping d0,d1=(row g, col 2t..), d2,d3=(row g+8) ----
    const int g  = lid >> 2;
    const int tt = lid & 3;
    #pragma unroll
    for (int i = 0; i < 2; i++) {
        const int row0 = bm + wm * 32 + i * 16 + g;
        #pragma unroll
        for (int j = 0; j < 8; j++) {
            const int coll = wn * 64 + j * 8 + tt * 2;   // local col in [0,128)
            const int col  = bn + coll;
            const float b0 = sm_bias[coll];
            const float b1 = sm_bias[coll + 1];
            #pragma unroll
            for (int half = 0; half < 2; half++) {
                const int row = row0 + half * 8;
                float v0 = acc[i][j][2 * half + 0] + b0;
                float v1 = acc[i][j][2 * half + 1] + b1;
                if (EPI == 0) {
                    float2 v = make_float2(fmaxf(v0, 0.f), fmaxf(v1, 0.f));
                    *(float2*)&g_h1[(size_t)row * NOUT + col] = v;
                } else if (EPI == 2) {
                    float2 v = make_float2(v0, v1);
                    *(float2*)&Cout[(size_t)row * NOUT + col] = v;
                } else {
                    size_t ti = (size_t)row * NOUT + col;
                    float2 tv = *(const float2*)&g_t[ti];
                    float2 v;
                    v.x = tv.x * __fdividef(1.f, 1.f + __expf(-v0));
                    v.y = tv.y * __fdividef(1.f, 1.f + __expf(-v1));
                    *(float2*)&g_t[ti] = v;
                }
            }
        }
    }
}

// ---------------------------------------------------------------------------
// Launch
// ---------------------------------------------------------------------------
extern "C" void kernel_launch(void* const* d_in, const int* in_sizes, int n_in,
                              void* d_out, int out_size)
{
    const float* x  = (const float*)d_in[0];
    const float* W1 = (const float*)d_in[1];
    const float* b1 = (const float*)d_in[2];
    const float* W2 = (const float*)d_in[3];
    const float* b2 = (const float*)d_in[4];
    const float* W3 = (const float*)d_in[5];
    const float* b3 = (const float*)d_in[6];
    float* out = (float*)d_out;
    (void)in_sizes; (void)n_in; (void)out_size;

    const int SM_UNFOLD = 3 * Cch * Ww * 4;      // 172032
    const int SM_GEMM   = 2 * 40960 + 512;       // 82432
    cudaFuncSetAttribute(unfold_kernel, cudaFuncAttributeMaxDynamicSharedMemorySize, SM_UNFOLD);
    cudaFuncSetAttribute(gemm_mma<0, 0>, cudaFuncAttributeMaxDynamicSharedMemorySize, SM_GEMM);
    cudaFuncSetAttribute(gemm_mma<1, 1>, cudaFuncAttributeMaxDynamicSharedMemorySize, SM_GEMM);
    cudaFuncSetAttribute(gemm_mma<2, 0>, cudaFuncAttributeMaxDynamicSharedMemorySize, SM_GEMM);

    __nv_bfloat16 *w1h, *w1l, *w2h, *w2l, *w3h, *w3l;
    cudaGetSymbolAddress((void**)&w1h, g_W1T_hi);
    cudaGetSymbolAddress((void**)&w1l, g_W1T_lo);
    cudaGetSymbolAddress((void**)&w2h, g_W2T_hi);
    cudaGetSymbolAddress((void**)&w2l, g_W2T_lo);
    cudaGetSymbolAddress((void**)&w3h, g_W3T_hi);
    cudaGetSymbolAddress((void**)&w3l, g_W3T_lo);

    // weight transpose + bf16 split
    transpose_split<<<dim3(Cch / 32, Dd / 32), dim3(32, 8)>>>(W1, w1h, w1l, Dd, Cch);
    transpose_split<<<dim3(Dd / 32, Cch / 32), dim3(32, 8)>>>(W2, w2h, w2l, Cch, Dd);
    transpose_split<<<dim3(Cch / 32, Dd / 32), dim3(32, 8)>>>(W3, w3h, w3l, Dd, Cch);

    // unfold: x -> g_t (row-major [L][2304])
    unfold_kernel<<<Bsz * Hh, 256, SM_UNFOLD>>>(x);

    // GEMM1: h1 = relu(t @ W1 + b1)        M=25088, N=256,  K=2304
    gemm_mma<0, 0><<<dim3(Cch / 128, Lrows / 128), 256, SM_GEMM>>>(w1h, w1l, b1, nullptr);

    // GEMM2: t = t * sigmoid(h1 @ W2 + b2) M=25088, N=2304, K=256
    gemm_mma<1, 1><<<dim3(Dd / 128, Lrows / 128), 256, SM_GEMM>>>(w2h, w2l, b2, nullptr);

    // GEMM3: out = t @ W3 + b3             M=25088, N=256,  K=2304
    gemm_mma<2, 0><<<dim3(Cch / 128, Lrows / 128), 256, SM_GEMM>>>(w3h, w3l, b3, out);
}

// round 10
// speedup vs baseline: 2.9265x; 1.2675x over previous
#include <cuda_runtime.h>
#include <cuda_bf16.h>
#include <math.h>

// ---------------------------------------------------------------------------
// Problem constants
// ---------------------------------------------------------------------------
#define Bsz  8
#define Cch  256
#define Hh   56
#define Ww   56
#define Lrows (Bsz * Hh * Ww)   // 25088
#define Dd    (Cch * 9)         // 2304

// ---------------------------------------------------------------------------
// Global scratch (__device__ arrays: allocation-free rule)
// All activations stored as bf16 hi/lo splits (hi+lo reconstructs fp32 to 2^-16)
// ---------------------------------------------------------------------------
__device__ __nv_bfloat16 g_th [(size_t)Lrows * Dd];   // t hi; after GEMM2: (t*s) hi
__device__ __nv_bfloat16 g_tl [(size_t)Lrows * Dd];   // t lo; after GEMM2: (t*s) lo
__device__ __nv_bfloat16 g_h1h[(size_t)Lrows * Cch];  // relu(h1) hi
__device__ __nv_bfloat16 g_h1l[(size_t)Lrows * Cch];  // relu(h1) lo
// weights transposed to K-major [N][K], split into bf16 hi/lo
__device__ __nv_bfloat16 g_W1T_hi[Cch * Dd], g_W1T_lo[Cch * Dd];
__device__ __nv_bfloat16 g_W2T_hi[Dd * Cch], g_W2T_lo[Dd * Cch];
__device__ __nv_bfloat16 g_W3T_hi[Cch * Dd], g_W3T_lo[Cch * Dd];

// ---------------------------------------------------------------------------
// PTX helpers (sm_80-era: compile at plain sm_103 target)
// ---------------------------------------------------------------------------
__device__ __forceinline__ unsigned smem_u32(const void* p) {
    unsigned a;
    asm("{ .reg .u64 t; cvta.to.shared.u64 t, %1; cvt.u32.u64 %0, t; }" : "=r"(a) : "l"(p));
    return a;
}
__device__ __forceinline__ void ldsm4(unsigned addr, unsigned r[4]) {
    asm volatile("ldmatrix.sync.aligned.m8n8.x4.shared.b16 {%0,%1,%2,%3}, [%4];"
        : "=r"(r[0]), "=r"(r[1]), "=r"(r[2]), "=r"(r[3]) : "r"(addr));
}
__device__ __forceinline__ void mma16816(float d[4], const unsigned a[4],
                                         unsigned b0, unsigned b1) {
    asm volatile("mma.sync.aligned.m16n8k16.row.col.f32.bf16.bf16.f32 "
        "{%0,%1,%2,%3}, {%4,%5,%6,%7}, {%8,%9}, {%0,%1,%2,%3};"
        : "+f"(d[0]), "+f"(d[1]), "+f"(d[2]), "+f"(d[3])
        : "r"(a[0]), "r"(a[1]), "r"(a[2]), "r"(a[3]), "r"(b0), "r"(b1));
}
#define CP_ASYNC16(dst, src) \
    asm volatile("cp.async.cg.shared.global [%0], [%1], 16;" \
                 :: "r"(dst), "l"(src) : "memory")
#define CP_COMMIT() asm volatile("cp.async.commit_group;" ::: "memory")
#define CP_WAIT0()  asm volatile("cp.async.wait_group 0;" ::: "memory")

// bf16 hi/lo split of a float pair, packed into one b32 each (low half = first elem)
__device__ __forceinline__ void split2(float x, float y, unsigned& h, unsigned& l) {
    __nv_bfloat16 hx = __float2bfloat16(x);
    __nv_bfloat16 hy = __float2bfloat16(y);
    float rx = x - __bfloat162float(hx);
    float ry = y - __bfloat162float(hy);
    __nv_bfloat162 hp; hp.x = hx; hp.y = hy;
    __nv_bfloat162 lp; lp.x = __float2bfloat16(rx); lp.y = __float2bfloat16(ry);
    h = *(unsigned*)&hp;
    l = *(unsigned*)&lp;
}

// ---------------------------------------------------------------------------
// Kernel: transpose + bf16-split weights  W[K][N] -> T_hi/T_lo [N][K]
// ---------------------------------------------------------------------------
__global__ void transpose_split(const float* __restrict__ W,
                                __nv_bfloat16* __restrict__ Thi,
                                __nv_bfloat16* __restrict__ Tlo,
                                int K, int N)
{
    __shared__ float tile[32][33];
    int n0 = blockIdx.x * 32;
    int k0 = blockIdx.y * 32;
    int tx = threadIdx.x, ty = threadIdx.y;
    #pragma unroll
    for (int r = 0; r < 32; r += 8)
        tile[ty + r][tx] = W[(size_t)(k0 + ty + r) * N + n0 + tx];
    __syncthreads();
    #pragma unroll
    for (int r = 0; r < 32; r += 8) {
        int n = n0 + ty + r;
        int k = k0 + tx;
        float v = tile[tx][ty + r];
        __nv_bfloat16 h = __float2bfloat16(v);
        Thi[(size_t)n * K + k] = h;
        Tlo[(size_t)n * K + k] = __float2bfloat16(v - __bfloat162float(h));
    }
}

// ---------------------------------------------------------------------------
// Kernel: unfold3x3 (pad=1) -> g_th/g_tl ROW-major [L][2304] (d = c*9+ki*3+kj)
// Block per (b, i, channel-quarter): 576 threads, 43 KB smem, 3 CTAs/SM.
// ---------------------------------------------------------------------------
__global__ void unfold_kernel(const float* __restrict__ x) {
    __shared__ float xs[3 * 64 * Ww];        // 43008 B
    const int CQ = 64;                       // channels per block
    const int RSZ = CQ * Ww;                 // 3584
    int b = blockIdx.x / Hh;
    int i = blockIdx.x % Hh;
    int q = blockIdx.y;                      // 0..3
    int tid = threadIdx.x;                   // 0..575

    for (int idx = tid; idx < 3 * RSZ; idx += 576) {
        int ki  = idx / RSZ;
        int rem = idx - ki * RSZ;
        int cl = rem / Ww;
        int j  = rem - cl * Ww;
        int ii = i + ki - 1;
        float v = 0.f;
        if (ii >= 0 && ii < Hh)
            v = x[(size_t)(b * Cch + q * CQ + cl) * (Hh * Ww) + ii * Ww + j];
        xs[idx] = v;
    }
    __syncthreads();

    // this thread's feature slot: d_global = q*576 + tid
    const int dg = q * 576 + tid;
    const int c  = dg / 9;
    const int r  = dg - c * 9;
    const int ki = r / 3;
    const int kj = r - ki * 3;
    const int soff = ki * RSZ + (c - q * CQ) * Ww;

    for (int j = 0; j < Ww; j++) {
        int jj = j + kj - 1;
        float v = (jj >= 0 && jj < Ww) ? xs[soff + jj] : 0.f;
        __nv_bfloat16 h = __float2bfloat16(v);
        __nv_bfloat16 l = __float2bfloat16(v - __bfloat162float(h));
        size_t o = ((size_t)(b * Hh + i) * Ww + j) * Dd + dg;
        g_th[o] = h;
        g_tl[o] = l;
    }
}

// ---------------------------------------------------------------------------
// HMMA GEMM: C[M=25088, N] = act(A[M,K] @ B^T + bias)
//   A pre-split bf16 hi/lo K-major-row [M][K]; B pre-split bf16 [N][K]
//   3-term split in fp32 acc: Ah*Bh + Ah*Bl + Al*Bh
// Tile BM=128 x BN=128 x BK=32, 256 threads (8 warps 4m x 2n, warp 32x64),
// 80B-padded smem rows (conflict-free ldmatrix), cp.async double buffer.
// EPI: 0 relu->g_h1h/l, 1 t*sigmoid->g_th/l in place, 2 bias->Cout fp32
// ---------------------------------------------------------------------------
template<int KD, int EPI>
__global__ __launch_bounds__(256, 2) void gemm_mma(
    const __nv_bfloat16* __restrict__ Ah_g,
    const __nv_bfloat16* __restrict__ Al_g,
    const __nv_bfloat16* __restrict__ Bh_g,
    const __nv_bfloat16* __restrict__ Bl_g,
    const float* __restrict__ bias,
    float* __restrict__ Cout)
{
    constexpr int BM = 128, BN = 128, BK = 32;
    constexpr int NT = KD / BK;
    constexpr int NOUT = (EPI == 1) ? Dd : Cch;
    constexpr unsigned ROWB = 80;                 // padded smem row bytes
    constexpr unsigned MATB = 128 * ROWB;         // 10240
    constexpr unsigned OFF_AH = 0, OFF_AL = MATB, OFF_BH = 2 * MATB, OFF_BL = 3 * MATB;
    constexpr unsigned STAGE = 4 * MATB;          // 40960
    constexpr unsigned OFF_BIAS = 2 * STAGE;      // 81920

    extern __shared__ char smem[];
    const unsigned sb = smem_u32(smem);
    float* sm_bias = (float*)(smem + OFF_BIAS);

    const int tid = threadIdx.x;
    const int wid = tid >> 5;
    const int lid = tid & 31;
    const int wm  = wid & 3;
    const int wn  = wid >> 2;
    const int bm  = blockIdx.y * BM;
    const int bn  = blockIdx.x * BN;

    const int srow  = tid >> 1;
    const int shalf = tid & 1;
    const unsigned sts_off = (unsigned)srow * ROWB + (unsigned)shalf * 32;

    const unsigned a_lane = (unsigned)((((lid >> 3) & 1) * 8 + (lid & 7))) * ROWB
                          + (unsigned)(lid >> 4) * 16;
    const unsigned b_lane = (unsigned)((((lid >> 4) & 1) * 8 + (lid & 7))) * ROWB
                          + (unsigned)((lid >> 3) & 1) * 16;

    if (tid < BN) sm_bias[tid] = bias[bn + tid];

    // per-thread global source bases (advance by BK per tile)
    const __nv_bfloat16* pAh = Ah_g + (size_t)(bm + srow) * KD + shalf * 16;
    const __nv_bfloat16* pAl = Al_g + (size_t)(bm + srow) * KD + shalf * 16;
    const __nv_bfloat16* pBh = Bh_g + (size_t)(bn + srow) * KD + shalf * 16;
    const __nv_bfloat16* pBl = Bl_g + (size_t)(bn + srow) * KD + shalf * 16;

    float acc[2][8][4];
    #pragma unroll
    for (int i = 0; i < 2; i++)
        #pragma unroll
        for (int j = 0; j < 8; j++)
            #pragma unroll
            for (int v = 0; v < 4; v++)
                acc[i][j][v] = 0.f;

    // prologue: stage tile 0 into buffer 0
    {
        unsigned d = sb + sts_off;
        CP_ASYNC16(d + OFF_AH,      pAh);
        CP_ASYNC16(d + OFF_AH + 16, pAh + 8);
        CP_ASYNC16(d + OFF_AL,      pAl);
        CP_ASYNC16(d + OFF_AL + 16, pAl + 8);
        CP_ASYNC16(d + OFF_BH,      pBh);
        CP_ASYNC16(d + OFF_BH + 16, pBh + 8);
        CP_ASYNC16(d + OFF_BL,      pBl);
        CP_ASYNC16(d + OFF_BL + 16, pBl + 8);
        CP_COMMIT();
    }
    CP_WAIT0();
    __syncthreads();

    for (int t = 0; t < NT; t++) {
        const unsigned so = (t & 1) ? STAGE : 0;
        const bool has_next = (t + 1 < NT);

        if (has_next) {
            const int k0 = (t + 1) * BK;
            unsigned d = sb + ((t & 1) ? 0u : STAGE) + sts_off;
            CP_ASYNC16(d + OFF_AH,      pAh + k0);
            CP_ASYNC16(d + OFF_AH + 16, pAh + k0 + 8);
            CP_ASYNC16(d + OFF_AL,      pAl + k0);
            CP_ASYNC16(d + OFF_AL + 16, pAl + k0 + 8);
            CP_ASYNC16(d + OFF_BH,      pBh + k0);
            CP_ASYNC16(d + OFF_BH + 16, pBh + k0 + 8);
            CP_ASYNC16(d + OFF_BL,      pBl + k0);
            CP_ASYNC16(d + OFF_BL + 16, pBl + k0 + 8);
            CP_COMMIT();
        }

        #pragma unroll
        for (int ks = 0; ks < 2; ks++) {
            const unsigned kso = (unsigned)ks * 32;
            unsigned Ah[2][4], Al[2][4];
            #pragma unroll
            for (int i = 0; i < 2; i++) {
                unsigned arow = (unsigned)(wm * 32 + i * 16) * ROWB + kso;
                ldsm4(sb + so + OFF_AH + arow + a_lane, Ah[i]);
                ldsm4(sb + so + OFF_AL + arow + a_lane, Al[i]);
            }
            unsigned Bh[4][4], Bl[4][4];
            #pragma unroll
            for (int g = 0; g < 4; g++) {
                unsigned brow = (unsigned)(wn * 64 + g * 16) * ROWB + kso;
                ldsm4(sb + so + OFF_BH + brow + b_lane, Bh[g]);
                ldsm4(sb + so + OFF_BL + brow + b_lane, Bl[g]);
            }
            #pragma unroll
            for (int i = 0; i < 2; i++) {
                #pragma unroll
                for (int g = 0; g < 4; g++) {
                    mma16816(acc[i][2 * g],     Ah[i], Bh[g][0], Bh[g][1]);
                    mma16816(acc[i][2 * g + 1], Ah[i], Bh[g][2], Bh[g][3]);
                    mma16816(acc[i][2 * g],     Ah[i], Bl[g][0], Bl[g][1]);
                    mma16816(acc[i][2 * g + 1], Ah[i], Bl[g][2], Bl[g][3]);
                    mma16816(acc[i][2 * g],     Al[i], Bh[g][0], Bh[g][1]);
                    mma16816(acc[i][2 * g + 1], Al[i], Bh[g][2], Bh[g][3]);
                }
            }
        }

        if (has_next) {
            CP_WAIT0();
            __syncthreads();
        }
    }

    // ---- epilogue ----
    const int g  = lid >> 2;
    const int tt = lid & 3;
    #pragma unroll
    for (int i = 0; i < 2; i++) {
        const int row0 = bm + wm * 32 + i * 16 + g;
        #pragma unroll
        for (int j = 0; j < 8; j++) {
            const int coll = wn * 64 + j * 8 + tt * 2;
            const int col  = bn + coll;
            const float b0 = sm_bias[coll];
            const float b1 = sm_bias[coll + 1];
            #pragma unroll
            for (int half = 0; half < 2; half++) {
                const int row = row0 + half * 8;
                float v0 = acc[i][j][2 * half + 0] + b0;
                float v1 = acc[i][j][2 * half + 1] + b1;
                if (EPI == 0) {
                    unsigned h, l;
                    split2(fmaxf(v0, 0.f), fmaxf(v1, 0.f), h, l);
                    size_t o = (size_t)row * NOUT + col;
                    *(unsigned*)&g_h1h[o] = h;
                    *(unsigned*)&g_h1l[o] = l;
                } else if (EPI == 2) {
                    float2 v = make_float2(v0, v1);
                    *(float2*)&Cout[(size_t)row * NOUT + col] = v;
                } else {
                    size_t o = (size_t)row * NOUT + col;
                    __nv_bfloat162 thp = *(__nv_bfloat162*)&g_th[o];
                    __nv_bfloat162 tlp = *(__nv_bfloat162*)&g_tl[o];
                    float t0 = __bfloat162float(thp.x) + __bfloat162float(tlp.x);
                    float t1 = __bfloat162float(thp.y) + __bfloat162float(tlp.y);
                    float ts0 = t0 * __fdividef(1.f, 1.f + __expf(-v0));
                    float ts1 = t1 * __fdividef(1.f, 1.f + __expf(-v1));
                    unsigned h, l;
                    split2(ts0, ts1, h, l);
                    *(unsigned*)&g_th[o] = h;
                    *(unsigned*)&g_tl[o] = l;
                }
            }
        }
    }
}

// ---------------------------------------------------------------------------
// Launch
// ---------------------------------------------------------------------------
extern "C" void kernel_launch(void* const* d_in, const int* in_sizes, int n_in,
                              void* d_out, int out_size)
{
    const float* x  = (const float*)d_in[0];
    const float* W1 = (const float*)d_in[1];
    const float* b1 = (const float*)d_in[2];
    const float* W2 = (const float*)d_in[3];
    const float* b2 = (const float*)d_in[4];
    const float* W3 = (const float*)d_in[5];
    const float* b3 = (const float*)d_in[6];
    float* out = (float*)d_out;
    (void)in_sizes; (void)n_in; (void)out_size;

    const int SM_GEMM = 2 * 40960 + 512;   // 82432
    cudaFuncSetAttribute(gemm_mma<Dd,  0>, cudaFuncAttributeMaxDynamicSharedMemorySize, SM_GEMM);
    cudaFuncSetAttribute(gemm_mma<Cch, 1>, cudaFuncAttributeMaxDynamicSharedMemorySize, SM_GEMM);
    cudaFuncSetAttribute(gemm_mma<Dd,  2>, cudaFuncAttributeMaxDynamicSharedMemorySize, SM_GEMM);

    __nv_bfloat16 *w1h, *w1l, *w2h, *w2l, *w3h, *w3l, *th, *tl, *h1h, *h1l;
    cudaGetSymbolAddress((void**)&w1h, g_W1T_hi);
    cudaGetSymbolAddress((void**)&w1l, g_W1T_lo);
    cudaGetSymbolAddress((void**)&w2h, g_W2T_hi);
    cudaGetSymbolAddress((void**)&w2l, g_W2T_lo);
    cudaGetSymbolAddress((void**)&w3h, g_W3T_hi);
    cudaGetSymbolAddress((void**)&w3l, g_W3T_lo);
    cudaGetSymbolAddress((void**)&th,  g_th);
    cudaGetSymbolAddress((void**)&tl,  g_tl);
    cudaGetSymbolAddress((void**)&h1h, g_h1h);
    cudaGetSymbolAddress((void**)&h1l, g_h1l);

    // weight transpose + bf16 split
    transpose_split<<<dim3(Cch / 32, Dd / 32), dim3(32, 8)>>>(W1, w1h, w1l, Dd, Cch);
    transpose_split<<<dim3(Dd / 32, Cch / 32), dim3(32, 8)>>>(W2, w2h, w2l, Cch, Dd);
    transpose_split<<<dim3(Cch / 32, Dd / 32), dim3(32, 8)>>>(W3, w3h, w3l, Dd, Cch);

    // unfold: x -> g_th/g_tl (row-major [L][2304], bf16 split)
    unfold_kernel<<<dim3(Bsz * Hh, 4), 576>>>(x);

    // GEMM1: h1 = relu(t @ W1 + b1)        M=25088, N=256,  K=2304
    gemm_mma<Dd, 0><<<dim3(Cch / 128, Lrows / 128), 256, SM_GEMM>>>(
        th, tl, w1h, w1l, b1, nullptr);

    // GEMM2: t = t * sigmoid(h1 @ W2 + b2) M=25088, N=2304, K=256
    gemm_mma<Cch, 1><<<dim3(Dd / 128, Lrows / 128), 256, SM_GEMM>>>(
        h1h, h1l, w2h, w2l, b2, nullptr);

    // GEMM3: out = ts @ W3 + b3            M=25088, N=256,  K=2304
    gemm_mma<Dd, 2><<<dim3(Cch / 128, Lrows / 128), 256, SM_GEMM>>>(
        th, tl, w3h, w3l, b3, out);
}

// round 11
// speedup vs baseline: 2.9514x; 1.0085x over previous
#include <cuda_runtime.h>
#include <cuda_bf16.h>
#include <math.h>

// ---------------------------------------------------------------------------
// Problem constants
// ---------------------------------------------------------------------------
#define Bsz  8
#define Cch  256
#define Hh   56
#define Ww   56
#define Lrows (Bsz * Hh * Ww)   // 25088
#define Dd    (Cch * 9)         // 2304

// ---------------------------------------------------------------------------
// Global scratch (__device__ arrays: allocation-free rule)
// All activations stored as bf16 hi/lo splits (hi+lo reconstructs fp32 to 2^-16)
// ---------------------------------------------------------------------------
__device__ __nv_bfloat16 g_th [(size_t)Lrows * Dd];   // t hi; after GEMM2: (t*s) hi
__device__ __nv_bfloat16 g_tl [(size_t)Lrows * Dd];   // t lo; after GEMM2: (t*s) lo
__device__ __nv_bfloat16 g_h1h[(size_t)Lrows * Cch];  // relu(h1) hi
__device__ __nv_bfloat16 g_h1l[(size_t)Lrows * Cch];  // relu(h1) lo
// weights transposed to K-major [N][K], split into bf16 hi/lo
__device__ __nv_bfloat16 g_W1T_hi[Cch * Dd], g_W1T_lo[Cch * Dd];
__device__ __nv_bfloat16 g_W2T_hi[Dd * Cch], g_W2T_lo[Dd * Cch];
__device__ __nv_bfloat16 g_W3T_hi[Cch * Dd], g_W3T_lo[Cch * Dd];

// ---------------------------------------------------------------------------
// PTX helpers (sm_80-era: compile at plain sm_103 target)
// ---------------------------------------------------------------------------
__device__ __forceinline__ unsigned smem_u32(const void* p) {
    unsigned a;
    asm("{ .reg .u64 t; cvta.to.shared.u64 t, %1; cvt.u32.u64 %0, t; }" : "=r"(a) : "l"(p));
    return a;
}
// NOT volatile: ordering vs smem writes is enforced by the memory-clobbered
// CP_WAIT0/__syncthreads barriers; letting the compiler schedule these under
// the MMAs is intentional.
__device__ __forceinline__ void ldsm4(unsigned addr, unsigned r[4]) {
    asm("ldmatrix.sync.aligned.m8n8.x4.shared.b16 {%0,%1,%2,%3}, [%4];"
        : "=r"(r[0]), "=r"(r[1]), "=r"(r[2]), "=r"(r[3]) : "r"(addr));
}
// NOT volatile: pure register dataflow; lets ptxas interleave independent MMAs.
__device__ __forceinline__ void mma16816(float d[4], const unsigned a[4],
                                         unsigned b0, unsigned b1) {
    asm("mma.sync.aligned.m16n8k16.row.col.f32.bf16.bf16.f32 "
        "{%0,%1,%2,%3}, {%4,%5,%6,%7}, {%8,%9}, {%0,%1,%2,%3};"
        : "+f"(d[0]), "+f"(d[1]), "+f"(d[2]), "+f"(d[3])
        : "r"(a[0]), "r"(a[1]), "r"(a[2]), "r"(a[3]), "r"(b0), "r"(b1));
}
#define CP_ASYNC16(dst, src) \
    asm volatile("cp.async.cg.shared.global [%0], [%1], 16;" \
                 :: "r"(dst), "l"(src) : "memory")
#define CP_COMMIT() asm volatile("cp.async.commit_group;" ::: "memory")
#define CP_WAIT0()  asm volatile("cp.async.wait_group 0;" ::: "memory")

// bf16 hi/lo split of a float pair, packed into one b32 each (low half = first elem)
__device__ __forceinline__ void split2(float x, float y, unsigned& h, unsigned& l) {
    __nv_bfloat16 hx = __float2bfloat16(x);
    __nv_bfloat16 hy = __float2bfloat16(y);
    float rx = x - __bfloat162float(hx);
    float ry = y - __bfloat162float(hy);
    __nv_bfloat162 hp; hp.x = hx; hp.y = hy;
    __nv_bfloat162 lp; lp.x = __float2bfloat16(rx); lp.y = __float2bfloat16(ry);
    h = *(unsigned*)&hp;
    l = *(unsigned*)&lp;
}

// ---------------------------------------------------------------------------
// Kernel: transpose + bf16-split weights  W[K][N] -> T_hi/T_lo [N][K]
// ---------------------------------------------------------------------------
__global__ void transpose_split(const float* __restrict__ W,
                                __nv_bfloat16* __restrict__ Thi,
                                __nv_bfloat16* __restrict__ Tlo,
                                int K, int N)
{
    __shared__ float tile[32][33];
    int n0 = blockIdx.x * 32;
    int k0 = blockIdx.y * 32;
    int tx = threadIdx.x, ty = threadIdx.y;
    #pragma unroll
    for (int r = 0; r < 32; r += 8)
        tile[ty + r][tx] = W[(size_t)(k0 + ty + r) * N + n0 + tx];
    __syncthreads();
    #pragma unroll
    for (int r = 0; r < 32; r += 8) {
        int n = n0 + ty + r;
        int k = k0 + tx;
        float v = tile[tx][ty + r];
        __nv_bfloat16 h = __float2bfloat16(v);
        Thi[(size_t)n * K + k] = h;
        Tlo[(size_t)n * K + k] = __float2bfloat16(v - __bfloat162float(h));
    }
}

// ---------------------------------------------------------------------------
// Kernel: unfold3x3 (pad=1) -> g_th/g_tl ROW-major [L][2304] (d = c*9+ki*3+kj)
// Block per (b, i, channel-quarter): 576 threads, 43 KB smem, 3 CTAs/SM.
// ---------------------------------------------------------------------------
__global__ void unfold_kernel(const float* __restrict__ x) {
    __shared__ float xs[3 * 64 * Ww];        // 43008 B
    const int CQ = 64;                       // channels per block
    const int RSZ = CQ * Ww;                 // 3584
    int b = blockIdx.x / Hh;
    int i = blockIdx.x % Hh;
    int q = blockIdx.y;                      // 0..3
    int tid = threadIdx.x;                   // 0..575

    for (int idx = tid; idx < 3 * RSZ; idx += 576) {
        int ki  = idx / RSZ;
        int rem = idx - ki * RSZ;
        int cl = rem / Ww;
        int j  = rem - cl * Ww;
        int ii = i + ki - 1;
        float v = 0.f;
        if (ii >= 0 && ii < Hh)
            v = x[(size_t)(b * Cch + q * CQ + cl) * (Hh * Ww) + ii * Ww + j];
        xs[idx] = v;
    }
    __syncthreads();

    // this thread's feature slot: d_global = q*576 + tid
    const int dg = q * 576 + tid;
    const int c  = dg / 9;
    const int r  = dg - c * 9;
    const int ki = r / 3;
    const int kj = r - ki * 3;
    const int soff = ki * RSZ + (c - q * CQ) * Ww;

    for (int j = 0; j < Ww; j++) {
        int jj = j + kj - 1;
        float v = (jj >= 0 && jj < Ww) ? xs[soff + jj] : 0.f;
        __nv_bfloat16 h = __float2bfloat16(v);
        __nv_bfloat16 l = __float2bfloat16(v - __bfloat162float(h));
        size_t o = ((size_t)(b * Hh + i) * Ww + j) * Dd + dg;
        g_th[o] = h;
        g_tl[o] = l;
    }
}

// ---------------------------------------------------------------------------
// HMMA GEMM: C[M=25088, N] = act(A[M,K] @ B^T + bias)
//   A pre-split bf16 hi/lo K-major-row [M][K]; B pre-split bf16 [N][K]
//   3-term split in fp32 acc: Ah*Bh + Ah*Bl + Al*Bh
// Tile BM=128 x BN=128 x BK=32, 256 threads (8 warps 4m x 2n, warp 32x64),
// 80B-padded smem rows (conflict-free ldmatrix), cp.async double buffer.
// MMA issue ordered by split term: same-accumulator reuse distance = 16
// (was 2 with volatile asm -> serial HMMA dependency chains).
// EPI: 0 relu->g_h1h/l, 1 t*sigmoid->g_th/l in place, 2 bias->Cout fp32
// ---------------------------------------------------------------------------
template<int KD, int EPI>
__global__ __launch_bounds__(256, 2) void gemm_mma(
    const __nv_bfloat16* __restrict__ Ah_g,
    const __nv_bfloat16* __restrict__ Al_g,
    const __nv_bfloat16* __restrict__ Bh_g,
    const __nv_bfloat16* __restrict__ Bl_g,
    const float* __restrict__ bias,
    float* __restrict__ Cout)
{
    constexpr int BM = 128, BN = 128, BK = 32;
    constexpr int NT = KD / BK;
    constexpr int NOUT = (EPI == 1) ? Dd : Cch;
    constexpr unsigned ROWB = 80;                 // padded smem row bytes
    constexpr unsigned MATB = 128 * ROWB;         // 10240
    constexpr unsigned OFF_AH = 0, OFF_AL = MATB, OFF_BH = 2 * MATB, OFF_BL = 3 * MATB;
    constexpr unsigned STAGE = 4 * MATB;          // 40960
    constexpr unsigned OFF_BIAS = 2 * STAGE;      // 81920

    extern __shared__ char smem[];
    const unsigned sb = smem_u32(smem);
    float* sm_bias = (float*)(smem + OFF_BIAS);

    const int tid = threadIdx.x;
    const int wid = tid >> 5;
    const int lid = tid & 31;
    const int wm  = wid & 3;
    const int wn  = wid >> 2;
    const int bm  = blockIdx.y * BM;
    const int bn  = blockIdx.x * BN;

    const int srow  = tid >> 1;
    const int shalf = tid & 1;
    const unsigned sts_off = (unsigned)srow * ROWB + (unsigned)shalf * 32;

    const unsigned a_lane = (unsigned)((((lid >> 3) & 1) * 8 + (lid & 7))) * ROWB
                          + (unsigned)(lid >> 4) * 16;
    const unsigned b_lane = (unsigned)((((lid >> 4) & 1) * 8 + (lid & 7))) * ROWB
                          + (unsigned)((lid >> 3) & 1) * 16;

    if (tid < BN) sm_bias[tid] = bias[bn + tid];

    // per-thread global source bases (advance by BK per tile)
    const __nv_bfloat16* pAh = Ah_g + (size_t)(bm + srow) * KD + shalf * 16;
    const __nv_bfloat16* pAl = Al_g + (size_t)(bm + srow) * KD + shalf * 16;
    const __nv_bfloat16* pBh = Bh_g + (size_t)(bn + srow) * KD + shalf * 16;
    const __nv_bfloat16* pBl = Bl_g + (size_t)(bn + srow) * KD + shalf * 16;

    float acc[2][8][4];
    #pragma unroll
    for (int i = 0; i < 2; i++)
        #pragma unroll
        for (int j = 0; j < 8; j++)
            #pragma unroll
            for (int v = 0; v < 4; v++)
                acc[i][j][v] = 0.f;

    // prologue: stage tile 0 into buffer 0
    {
        unsigned d = sb + sts_off;
        CP_ASYNC16(d + OFF_AH,      pAh);
        CP_ASYNC16(d + OFF_AH + 16, pAh + 8);
        CP_ASYNC16(d + OFF_AL,      pAl);
        CP_ASYNC16(d + OFF_AL + 16, pAl + 8);
        CP_ASYNC16(d + OFF_BH,      pBh);
        CP_ASYNC16(d + OFF_BH + 16, pBh + 8);
        CP_ASYNC16(d + OFF_BL,      pBl);
        CP_ASYNC16(d + OFF_BL + 16, pBl + 8);
        CP_COMMIT();
    }
    CP_WAIT0();
    __syncthreads();

    for (int t = 0; t < NT; t++) {
        const unsigned so = (t & 1) ? STAGE : 0;
        const bool has_next = (t + 1 < NT);

        if (has_next) {
            const int k0 = (t + 1) * BK;
            unsigned d = sb + ((t & 1) ? 0u : STAGE) + sts_off;
            CP_ASYNC16(d + OFF_AH,      pAh + k0);
            CP_ASYNC16(d + OFF_AH + 16, pAh + k0 + 8);
            CP_ASYNC16(d + OFF_AL,      pAl + k0);
            CP_ASYNC16(d + OFF_AL + 16, pAl + k0 + 8);
            CP_ASYNC16(d + OFF_BH,      pBh + k0);
            CP_ASYNC16(d + OFF_BH + 16, pBh + k0 + 8);
            CP_ASYNC16(d + OFF_BL,      pBl + k0);
            CP_ASYNC16(d + OFF_BL + 16, pBl + k0 + 8);
            CP_COMMIT();
        }

        #pragma unroll
        for (int ks = 0; ks < 2; ks++) {
            const unsigned kso = (unsigned)ks * 32;
            unsigned Ah[2][4], Al[2][4];
            #pragma unroll
            for (int i = 0; i < 2; i++) {
                unsigned arow = (unsigned)(wm * 32 + i * 16) * ROWB + kso;
                ldsm4(sb + so + OFF_AH + arow + a_lane, Ah[i]);
                ldsm4(sb + so + OFF_AL + arow + a_lane, Al[i]);
            }
            unsigned Bh[4][4], Bl[4][4];
            #pragma unroll
            for (int g = 0; g < 4; g++) {
                unsigned brow = (unsigned)(wn * 64 + g * 16) * ROWB + kso;
                ldsm4(sb + so + OFF_BH + brow + b_lane, Bh[g]);
                ldsm4(sb + so + OFF_BL + brow + b_lane, Bl[g]);
            }
            // term 1: Ah * Bh  (16 independent accumulators)
            #pragma unroll
            for (int i = 0; i < 2; i++)
                #pragma unroll
                for (int g = 0; g < 4; g++) {
                    mma16816(acc[i][2 * g],     Ah[i], Bh[g][0], Bh[g][1]);
                    mma16816(acc[i][2 * g + 1], Ah[i], Bh[g][2], Bh[g][3]);
                }
            // term 2: Ah * Bl
            #pragma unroll
            for (int i = 0; i < 2; i++)
                #pragma unroll
                for (int g = 0; g < 4; g++) {
                    mma16816(acc[i][2 * g],     Ah[i], Bl[g][0], Bl[g][1]);
                    mma16816(acc[i][2 * g + 1], Ah[i], Bl[g][2], Bl[g][3]);
                }
            // term 3: Al * Bh
            #pragma unroll
            for (int i = 0; i < 2; i++)
                #pragma unroll
                for (int g = 0; g < 4; g++) {
                    mma16816(acc[i][2 * g],     Al[i], Bh[g][0], Bh[g][1]);
                    mma16816(acc[i][2 * g + 1], Al[i], Bh[g][2], Bh[g][3]);
                }
        }

        if (has_next) {
            CP_WAIT0();
            __syncthreads();
        }
    }

    // ---- epilogue ----
    const int g  = lid >> 2;
    const int tt = lid & 3;
    #pragma unroll
    for (int i = 0; i < 2; i++) {
        const int row0 = bm + wm * 32 + i * 16 + g;
        #pragma unroll
        for (int j = 0; j < 8; j++) {
            const int coll = wn * 64 + j * 8 + tt * 2;
            const int col  = bn + coll;
            const float b0 = sm_bias[coll];
            const float b1 = sm_bias[coll + 1];
            #pragma unroll
            for (int half = 0; half < 2; half++) {
                const int row = row0 + half * 8;
                float v0 = acc[i][j][2 * half + 0] + b0;
                float v1 = acc[i][j][2 * half + 1] + b1;
                if (EPI == 0) {
                    unsigned h, l;
                    split2(fmaxf(v0, 0.f), fmaxf(v1, 0.f), h, l);
                    size_t o = (size_t)row * NOUT + col;
                    *(unsigned*)&g_h1h[o] = h;
                    *(unsigned*)&g_h1l[o] = l;
                } else if (EPI == 2) {
                    float2 v = make_float2(v0, v1);
                    *(float2*)&Cout[(size_t)row * NOUT + col] = v;
                } else {
                    size_t o = (size_t)row * NOUT + col;
                    __nv_bfloat162 thp = *(__nv_bfloat162*)&g_th[o];
                    __nv_bfloat162 tlp = *(__nv_bfloat162*)&g_tl[o];
                    float t0 = __bfloat162float(thp.x) + __bfloat162float(tlp.x);
                    float t1 = __bfloat162float(thp.y) + __bfloat162float(tlp.y);
                    float ts0 = t0 * __fdividef(1.f, 1.f + __expf(-v0));
                    float ts1 = t1 * __fdividef(1.f, 1.f + __expf(-v1));
                    unsigned h, l;
                    split2(ts0, ts1, h, l);
                    *(unsigned*)&g_th[o] = h;
                    *(unsigned*)&g_tl[o] = l;
                }
            }
        }
    }
}

// ---------------------------------------------------------------------------
// Launch
// ---------------------------------------------------------------------------
extern "C" void kernel_launch(void* const* d_in, const int* in_sizes, int n_in,
                              void* d_out, int out_size)
{
    const float* x  = (const float*)d_in[0];
    const float* W1 = (const float*)d_in[1];
    const float* b1 = (const float*)d_in[2];
    const float* W2 = (const float*)d_in[3];
    const float* b2 = (const float*)d_in[4];
    const float* W3 = (const float*)d_in[5];
    const float* b3 = (const float*)d_in[6];
    float* out = (float*)d_out;
    (void)in_sizes; (void)n_in; (void)out_size;

    const int SM_GEMM = 2 * 40960 + 512;   // 82432
    cudaFuncSetAttribute(gemm_mma<Dd,  0>, cudaFuncAttributeMaxDynamicSharedMemorySize, SM_GEMM);
    cudaFuncSetAttribute(gemm_mma<Cch, 1>, cudaFuncAttributeMaxDynamicSharedMemorySize, SM_GEMM);
    cudaFuncSetAttribute(gemm_mma<Dd,  2>, cudaFuncAttributeMaxDynamicSharedMemorySize, SM_GEMM);

    __nv_bfloat16 *w1h, *w1l, *w2h, *w2l, *w3h, *w3l, *th, *tl, *h1h, *h1l;
    cudaGetSymbolAddress((void**)&w1h, g_W1T_hi);
    cudaGetSymbolAddress((void**)&w1l, g_W1T_lo);
    cudaGetSymbolAddress((void**)&w2h, g_W2T_hi);
    cudaGetSymbolAddress((void**)&w2l, g_W2T_lo);
    cudaGetSymbolAddress((void**)&w3h, g_W3T_hi);
    cudaGetSymbolAddress((void**)&w3l, g_W3T_lo);
    cudaGetSymbolAddress((void**)&th,  g_th);
    cudaGetSymbolAddress((void**)&tl,  g_tl);
    cudaGetSymbolAddress((void**)&h1h, g_h1h);
    cudaGetSymbolAddress((void**)&h1l, g_h1l);

    // weight transpose + bf16 split
    transpose_split<<<dim3(Cch / 32, Dd / 32), dim3(32, 8)>>>(W1, w1h, w1l, Dd, Cch);
    transpose_split<<<dim3(Dd / 32, Cch / 32), dim3(32, 8)>>>(W2, w2h, w2l, Cch, Dd);
    transpose_split<<<dim3(Cch / 32, Dd / 32), dim3(32, 8)>>>(W3, w3h, w3l, Dd, Cch);

    // unfold: x -> g_th/g_tl (row-major [L][2304], bf16 split)
    unfold_kernel<<<dim3(Bsz * Hh, 4), 576>>>(x);

    // GEMM1: h1 = relu(t @ W1 + b1)        M=25088, N=256,  K=2304
    gemm_mma<Dd, 0><<<dim3(Cch / 128, Lrows / 128), 256, SM_GEMM>>>(
        th, tl, w1h, w1l, b1, nullptr);

    // GEMM2: t = t * sigmoid(h1 @ W2 + b2) M=25088, N=2304, K=256
    gemm_mma<Cch, 1><<<dim3(Dd / 128, Lrows / 128), 256, SM_GEMM>>>(
        h1h, h1l, w2h, w2l, b2, nullptr);

    // GEMM3: out = ts @ W3 + b3            M=25088, N=256,  K=2304
    gemm_mma<Dd, 2><<<dim3(Cch / 128, Lrows / 128), 256, SM_GEMM>>>(
        th, tl, w3h, w3l, b3, out);
}

// round 12
// speedup vs baseline: 4.3369x; 1.4694x over previous
#include <cuda_runtime.h>
#include <cuda_fp16.h>
#include <math.h>

// ---------------------------------------------------------------------------
// Problem constants
// ---------------------------------------------------------------------------
#define Bsz  8
#define Cch  256
#define Hh   56
#define Ww   56
#define Lrows (Bsz * Hh * Ww)   // 25088
#define Dd    (Cch * 9)         // 2304

// ---------------------------------------------------------------------------
// Global scratch (__device__ arrays: allocation-free rule)
// Activations: SINGLE fp16 (11-bit mantissa; norm rounding error ~2.8e-4).
// Weights: fp16 hi/lo split (22 bits, error 2^-22) -> 2-term MMA.
// ---------------------------------------------------------------------------
__device__ __half g_t16 [(size_t)Lrows * Dd];   // t; after GEMM2 holds t*s
__device__ __half g_h116[(size_t)Lrows * Cch];  // relu hidden
// weights transposed to K-major [N][K], split into fp16 hi/lo
__device__ __half g_W1T_hi[Cch * Dd], g_W1T_lo[Cch * Dd];
__device__ __half g_W2T_hi[Dd * Cch], g_W2T_lo[Dd * Cch];
__device__ __half g_W3T_hi[Cch * Dd], g_W3T_lo[Cch * Dd];

// ---------------------------------------------------------------------------
// PTX helpers (sm_80-era: compile at plain sm_103 target)
// ---------------------------------------------------------------------------
__device__ __forceinline__ unsigned smem_u32(const void* p) {
    unsigned a;
    asm("{ .reg .u64 t; cvta.to.shared.u64 t, %1; cvt.u32.u64 %0, t; }" : "=r"(a) : "l"(p));
    return a;
}
__device__ __forceinline__ void ldsm4(unsigned addr, unsigned r[4]) {
    asm("ldmatrix.sync.aligned.m8n8.x4.shared.b16 {%0,%1,%2,%3}, [%4];"
        : "=r"(r[0]), "=r"(r[1]), "=r"(r[2]), "=r"(r[3]) : "r"(addr));
}
__device__ __forceinline__ void mma16816(float d[4], const unsigned a[4],
                                         unsigned b0, unsigned b1) {
    asm("mma.sync.aligned.m16n8k16.row.col.f32.f16.f16.f32 "
        "{%0,%1,%2,%3}, {%4,%5,%6,%7}, {%8,%9}, {%0,%1,%2,%3};"
        : "+f"(d[0]), "+f"(d[1]), "+f"(d[2]), "+f"(d[3])
        : "r"(a[0]), "r"(a[1]), "r"(a[2]), "r"(a[3]), "r"(b0), "r"(b1));
}
#define CP_ASYNC16(dst, src) \
    asm volatile("cp.async.cg.shared.global [%0], [%1], 16;" \
                 :: "r"(dst), "l"(src) : "memory")
#define CP_COMMIT() asm volatile("cp.async.commit_group;" ::: "memory")
#define CP_WAIT0()  asm volatile("cp.async.wait_group 0;" ::: "memory")

// ---------------------------------------------------------------------------
// Kernel: transpose + fp16-split weights  W[K][N] -> T_hi/T_lo [N][K]
// ---------------------------------------------------------------------------
__global__ void transpose_split(const float* __restrict__ W,
                                __half* __restrict__ Thi,
                                __half* __restrict__ Tlo,
                                int K, int N)
{
    __shared__ float tile[32][33];
    int n0 = blockIdx.x * 32;
    int k0 = blockIdx.y * 32;
    int tx = threadIdx.x, ty = threadIdx.y;
    #pragma unroll
    for (int r = 0; r < 32; r += 8)
        tile[ty + r][tx] = W[(size_t)(k0 + ty + r) * N + n0 + tx];
    __syncthreads();
    #pragma unroll
    for (int r = 0; r < 32; r += 8) {
        int n = n0 + ty + r;
        int k = k0 + tx;
        float v = tile[tx][ty + r];
        __half h = __float2half(v);
        Thi[(size_t)n * K + k] = h;
        Tlo[(size_t)n * K + k] = __float2half(v - __half2float(h));
    }
}

// ---------------------------------------------------------------------------
// Kernel: unfold3x3 (pad=1) -> g_t16 ROW-major [L][2304] (d = c*9+ki*3+kj)
// Block per (b, i, channel-quarter): 576 threads, 43 KB smem.
// ---------------------------------------------------------------------------
__global__ void unfold_kernel(const float* __restrict__ x) {
    __shared__ float xs[3 * 64 * Ww];        // 43008 B
    const int CQ = 64;
    const int RSZ = CQ * Ww;                 // 3584
    int b = blockIdx.x / Hh;
    int i = blockIdx.x % Hh;
    int q = blockIdx.y;                      // 0..3
    int tid = threadIdx.x;                   // 0..575

    for (int idx = tid; idx < 3 * RSZ; idx += 576) {
        int ki  = idx / RSZ;
        int rem = idx - ki * RSZ;
        int cl = rem / Ww;
        int j  = rem - cl * Ww;
        int ii = i + ki - 1;
        float v = 0.f;
        if (ii >= 0 && ii < Hh)
            v = x[(size_t)(b * Cch + q * CQ + cl) * (Hh * Ww) + ii * Ww + j];
        xs[idx] = v;
    }
    __syncthreads();

    const int dg = q * 576 + tid;
    const int c  = dg / 9;
    const int r  = dg - c * 9;
    const int ki = r / 3;
    const int kj = r - ki * 3;
    const int soff = ki * RSZ + (c - q * CQ) * Ww;

    for (int j = 0; j < Ww; j++) {
        int jj = j + kj - 1;
        float v = (jj >= 0 && jj < Ww) ? xs[soff + jj] : 0.f;
        size_t o = ((size_t)(b * Hh + i) * Ww + j) * Dd + dg;
        g_t16[o] = __float2half(v);
    }
}

// ---------------------------------------------------------------------------
// HMMA GEMM: C[M=25088, N] = act(A[M,K] @ B^T + bias)
//   A single fp16 row-major [M][K]; B fp16 hi/lo split [N][K]
//   2-term: A*Bh + A*Bl accumulated in fp32 (weights exact to 2^-22;
//   total error dominated by activation fp16 rounding ~2.8e-4 norm)
// Tile BM=128 x BN=128 x BK=32, 256 threads (8 warps 4m x 2n, warp 32x64),
// 80B-padded smem rows (conflict-free ldmatrix), cp.async double buffer.
// EPI: 0 relu->g_h116, 1 t*sigmoid->g_t16 in place, 2 bias->Cout fp32
// ---------------------------------------------------------------------------
template<int KD, int EPI>
__global__ __launch_bounds__(256, 2) void gemm_mma(
    const __half* __restrict__ A_g,
    const __half* __restrict__ Bh_g,
    const __half* __restrict__ Bl_g,
    const float* __restrict__ bias,
    float* __restrict__ Cout)
{
    constexpr int BM = 128, BN = 128, BK = 32;
    constexpr int NT = KD / BK;
    constexpr int NOUT = (EPI == 1) ? Dd : Cch;
    constexpr unsigned ROWB = 80;                 // padded smem row bytes
    constexpr unsigned MATB = 128 * ROWB;         // 10240
    constexpr unsigned OFF_A = 0, OFF_BH = MATB, OFF_BL = 2 * MATB;
    constexpr unsigned STAGE = 3 * MATB;          // 30720
    constexpr unsigned OFF_BIAS = 2 * STAGE;      // 61440

    extern __shared__ char smem[];
    const unsigned sb = smem_u32(smem);
    float* sm_bias = (float*)(smem + OFF_BIAS);

    const int tid = threadIdx.x;
    const int wid = tid >> 5;
    const int lid = tid & 31;
    const int wm  = wid & 3;
    const int wn  = wid >> 2;
    const int bm  = blockIdx.y * BM;
    const int bn  = blockIdx.x * BN;

    const int srow  = tid >> 1;
    const int shalf = tid & 1;
    const unsigned sts_off = (unsigned)srow * ROWB + (unsigned)shalf * 32;

    const unsigned a_lane = (unsigned)((((lid >> 3) & 1) * 8 + (lid & 7))) * ROWB
                          + (unsigned)(lid >> 4) * 16;
    const unsigned b_lane = (unsigned)((((lid >> 4) & 1) * 8 + (lid & 7))) * ROWB
                          + (unsigned)((lid >> 3) & 1) * 16;

    if (tid < BN) sm_bias[tid] = bias[bn + tid];

    // per-thread global source bases (advance by BK per tile)
    const __half* pA  = A_g  + (size_t)(bm + srow) * KD + shalf * 16;
    const __half* pBh = Bh_g + (size_t)(bn + srow) * KD + shalf * 16;
    const __half* pBl = Bl_g + (size_t)(bn + srow) * KD + shalf * 16;

    float acc[2][8][4];
    #pragma unroll
    for (int i = 0; i < 2; i++)
        #pragma unroll
        for (int j = 0; j < 8; j++)
            #pragma unroll
            for (int v = 0; v < 4; v++)
                acc[i][j][v] = 0.f;

    // prologue: stage tile 0 into buffer 0
    {
        unsigned d = sb + sts_off;
        CP_ASYNC16(d + OFF_A,       pA);
        CP_ASYNC16(d + OFF_A  + 16, pA + 8);
        CP_ASYNC16(d + OFF_BH,      pBh);
        CP_ASYNC16(d + OFF_BH + 16, pBh + 8);
        CP_ASYNC16(d + OFF_BL,      pBl);
        CP_ASYNC16(d + OFF_BL + 16, pBl + 8);
        CP_COMMIT();
    }
    CP_WAIT0();
    __syncthreads();

    for (int t = 0; t < NT; t++) {
        const unsigned so = (t & 1) ? STAGE : 0;
        const bool has_next = (t + 1 < NT);

        if (has_next) {
            const int k0 = (t + 1) * BK;
            unsigned d = sb + ((t & 1) ? 0u : STAGE) + sts_off;
            CP_ASYNC16(d + OFF_A,       pA + k0);
            CP_ASYNC16(d + OFF_A  + 16, pA + k0 + 8);
            CP_ASYNC16(d + OFF_BH,      pBh + k0);
            CP_ASYNC16(d + OFF_BH + 16, pBh + k0 + 8);
            CP_ASYNC16(d + OFF_BL,      pBl + k0);
            CP_ASYNC16(d + OFF_BL + 16, pBl + k0 + 8);
            CP_COMMIT();
        }

        #pragma unroll
        for (int ks = 0; ks < 2; ks++) {
            const unsigned kso = (unsigned)ks * 32;
            unsigned Af[2][4];
            #pragma unroll
            for (int i = 0; i < 2; i++) {
                unsigned arow = (unsigned)(wm * 32 + i * 16) * ROWB + kso;
                ldsm4(sb + so + OFF_A + arow + a_lane, Af[i]);
            }
            unsigned Bh[4][4], Bl[4][4];
            #pragma unroll
            for (int g = 0; g < 4; g++) {
                unsigned brow = (unsigned)(wn * 64 + g * 16) * ROWB + kso;
                ldsm4(sb + so + OFF_BH + brow + b_lane, Bh[g]);
                ldsm4(sb + so + OFF_BL + brow + b_lane, Bl[g]);
            }
            // term 1: A * Bh  (16 independent accumulators)
            #pragma unroll
            for (int i = 0; i < 2; i++)
                #pragma unroll
                for (int g = 0; g < 4; g++) {
                    mma16816(acc[i][2 * g],     Af[i], Bh[g][0], Bh[g][1]);
                    mma16816(acc[i][2 * g + 1], Af[i], Bh[g][2], Bh[g][3]);
                }
            // term 2: A * Bl
            #pragma unroll
            for (int i = 0; i < 2; i++)
                #pragma unroll
                for (int g = 0; g < 4; g++) {
                    mma16816(acc[i][2 * g],     Af[i], Bl[g][0], Bl[g][1]);
                    mma16816(acc[i][2 * g + 1], Af[i], Bl[g][2], Bl[g][3]);
                }
        }

        if (has_next) {
            CP_WAIT0();
            __syncthreads();
        }
    }

    // ---- epilogue ----
    const int g  = lid >> 2;
    const int tt = lid & 3;
    #pragma unroll
    for (int i = 0; i < 2; i++) {
        const int row0 = bm + wm * 32 + i * 16 + g;
        #pragma unroll
        for (int j = 0; j < 8; j++) {
            const int coll = wn * 64 + j * 8 + tt * 2;
            const int col  = bn + coll;
            const float b0 = sm_bias[coll];
            const float b1 = sm_bias[coll + 1];
            #pragma unroll
            for (int half = 0; half < 2; half++) {
                const int row = row0 + half * 8;
                float v0 = acc[i][j][2 * half + 0] + b0;
                float v1 = acc[i][j][2 * half + 1] + b1;
                if (EPI == 0) {
                    __half2 h = __floats2half2_rn(fmaxf(v0, 0.f), fmaxf(v1, 0.f));
                    *(__half2*)&g_h116[(size_t)row * NOUT + col] = h;
                } else if (EPI == 2) {
                    float2 v = make_float2(v0, v1);
                    *(float2*)&Cout[(size_t)row * NOUT + col] = v;
                } else {
                    size_t o = (size_t)row * NOUT + col;
                    __half2 tp = *(__half2*)&g_t16[o];
                    float t0 = __half2float(__low2half(tp));
                    float t1 = __half2float(__high2half(tp));
                    float ts0 = t0 * __fdividef(1.f, 1.f + __expf(-v0));
                    float ts1 = t1 * __fdividef(1.f, 1.f + __expf(-v1));
                    *(__half2*)&g_t16[o] = __floats2half2_rn(ts0, ts1);
                }
            }
        }
    }
}

// ---------------------------------------------------------------------------
// Launch
// ---------------------------------------------------------------------------
extern "C" void kernel_launch(void* const* d_in, const int* in_sizes, int n_in,
                              void* d_out, int out_size)
{
    const float* x  = (const float*)d_in[0];
    const float* W1 = (const float*)d_in[1];
    const float* b1 = (const float*)d_in[2];
    const float* W2 = (const float*)d_in[3];
    const float* b2 = (const float*)d_in[4];
    const float* W3 = (const float*)d_in[5];
    const float* b3 = (const float*)d_in[6];
    float* out = (float*)d_out;
    (void)in_sizes; (void)n_in; (void)out_size;

    const int SM_GEMM = 2 * 30720 + 512;   // 61952
    cudaFuncSetAttribute(gemm_mma<Dd,  0>, cudaFuncAttributeMaxDynamicSharedMemorySize, SM_GEMM);
    cudaFuncSetAttribute(gemm_mma<Cch, 1>, cudaFuncAttributeMaxDynamicSharedMemorySize, SM_GEMM);
    cudaFuncSetAttribute(gemm_mma<Dd,  2>, cudaFuncAttributeMaxDynamicSharedMemorySize, SM_GEMM);

    __half *w1h, *w1l, *w2h, *w2l, *w3h, *w3l, *t16, *h116;
    cudaGetSymbolAddress((void**)&w1h, g_W1T_hi);
    cudaGetSymbolAddress((void**)&w1l, g_W1T_lo);
    cudaGetSymbolAddress((void**)&w2h, g_W2T_hi);
    cudaGetSymbolAddress((void**)&w2l, g_W2T_lo);
    cudaGetSymbolAddress((void**)&w3h, g_W3T_hi);
    cudaGetSymbolAddress((void**)&w3l, g_W3T_lo);
    cudaGetSymbolAddress((void**)&t16,  g_t16);
    cudaGetSymbolAddress((void**)&h116, g_h116);

    // weight transpose + fp16 split
    transpose_split<<<dim3(Cch / 32, Dd / 32), dim3(32, 8)>>>(W1, w1h, w1l, Dd, Cch);
    transpose_split<<<dim3(Dd / 32, Cch / 32), dim3(32, 8)>>>(W2, w2h, w2l, Cch, Dd);
    transpose_split<<<dim3(Cch / 32, Dd / 32), dim3(32, 8)>>>(W3, w3h, w3l, Dd, Cch);

    // unfold: x -> g_t16 (row-major [L][2304], single fp16)
    unfold_kernel<<<dim3(Bsz * Hh, 4), 576>>>(x);

    // GEMM1: h1 = relu(t @ W1 + b1)        M=25088, N=256,  K=2304
    gemm_mma<Dd, 0><<<dim3(Cch / 128, Lrows / 128), 256, SM_GEMM>>>(
        t16, w1h, w1l, b1, nullptr);

    // GEMM2: t = t * sigmoid(h1 @ W2 + b2) M=25088, N=2304, K=256
    gemm_mma<Cch, 1><<<dim3(Dd / 128, Lrows / 128), 256, SM_GEMM>>>(
        h116, w2h, w2l, b2, nullptr);

    // GEMM3: out = ts @ W3 + b3            M=25088, N=256,  K=2304
    gemm_mma<Dd, 2><<<dim3(Cch / 128, Lrows / 128), 256, SM_GEMM>>>(
        t16, w3h, w3l, b3, out);
}

// round 13
// speedup vs baseline: 5.8829x; 1.3565x over previous
#include <cuda_runtime.h>
#include <cuda_fp16.h>
#include <math.h>

// ---------------------------------------------------------------------------
// Problem constants
// ---------------------------------------------------------------------------
#define Bsz  8
#define Cch  256
#define Hh   56
#define Ww   56
#define Lrows (Bsz * Hh * Ww)   // 25088
#define Dd    (Cch * 9)         // 2304

// ---------------------------------------------------------------------------
// Global scratch (__device__ arrays: allocation-free rule)
// Everything single fp16: 1-term MMA. Norm error budget:
//   act rounding ~2.8e-4 (measured 2.95e-4 in R12) + weight rounding ~2.8e-4
//   -> ~4.2e-4 quadrature, under the 1e-3 gate with ~2x margin.
// ---------------------------------------------------------------------------
__device__ __half g_t16 [(size_t)Lrows * Dd];   // t; after GEMM2 holds t*s
__device__ __half g_h116[(size_t)Lrows * Cch];  // relu hidden
// weights transposed to K-major [N][K], single fp16
__device__ __half g_W1T[Cch * Dd];
__device__ __half g_W2T[Dd * Cch];
__device__ __half g_W3T[Cch * Dd];

// ---------------------------------------------------------------------------
// PTX helpers (sm_80-era: compile at plain sm_103 target)
// ---------------------------------------------------------------------------
__device__ __forceinline__ unsigned smem_u32(const void* p) {
    unsigned a;
    asm("{ .reg .u64 t; cvta.to.shared.u64 t, %1; cvt.u32.u64 %0, t; }" : "=r"(a) : "l"(p));
    return a;
}
__device__ __forceinline__ void ldsm4(unsigned addr, unsigned r[4]) {
    asm("ldmatrix.sync.aligned.m8n8.x4.shared.b16 {%0,%1,%2,%3}, [%4];"
        : "=r"(r[0]), "=r"(r[1]), "=r"(r[2]), "=r"(r[3]) : "r"(addr));
}
__device__ __forceinline__ void mma16816(float d[4], const unsigned a[4],
                                         unsigned b0, unsigned b1) {
    asm("mma.sync.aligned.m16n8k16.row.col.f32.f16.f16.f32 "
        "{%0,%1,%2,%3}, {%4,%5,%6,%7}, {%8,%9}, {%0,%1,%2,%3};"
        : "+f"(d[0]), "+f"(d[1]), "+f"(d[2]), "+f"(d[3])
        : "r"(a[0]), "r"(a[1]), "r"(a[2]), "r"(a[3]), "r"(b0), "r"(b1));
}
#define CP_ASYNC16(dst, src) \
    asm volatile("cp.async.cg.shared.global [%0], [%1], 16;" \
                 :: "r"(dst), "l"(src) : "memory")
#define CP_COMMIT() asm volatile("cp.async.commit_group;" ::: "memory")
#define CP_WAIT0()  asm volatile("cp.async.wait_group 0;" ::: "memory")

// ---------------------------------------------------------------------------
// Kernel: transpose weights to fp16  W[K][N] -> T [N][K]
// ---------------------------------------------------------------------------
__global__ void transpose_w(const float* __restrict__ W,
                            __half* __restrict__ T,
                            int K, int N)
{
    __shared__ float tile[32][33];
    int n0 = blockIdx.x * 32;
    int k0 = blockIdx.y * 32;
    int tx = threadIdx.x, ty = threadIdx.y;
    #pragma unroll
    for (int r = 0; r < 32; r += 8)
        tile[ty + r][tx] = W[(size_t)(k0 + ty + r) * N + n0 + tx];
    __syncthreads();
    #pragma unroll
    for (int r = 0; r < 32; r += 8) {
        int n = n0 + ty + r;
        int k = k0 + tx;
        T[(size_t)n * K + k] = __float2half(tile[tx][ty + r]);
    }
}

// ---------------------------------------------------------------------------
// Kernel: unfold3x3 (pad=1) -> g_t16 ROW-major [L][2304] (d = c*9+ki*3+kj)
// Block per (b, i, channel-quarter): 576 threads, 43 KB smem.
// ---------------------------------------------------------------------------
__global__ void unfold_kernel(const float* __restrict__ x) {
    __shared__ float xs[3 * 64 * Ww];        // 43008 B
    const int CQ = 64;
    const int RSZ = CQ * Ww;                 // 3584
    int b = blockIdx.x / Hh;
    int i = blockIdx.x % Hh;
    int q = blockIdx.y;                      // 0..3
    int tid = threadIdx.x;                   // 0..575

    for (int idx = tid; idx < 3 * RSZ; idx += 576) {
        int ki  = idx / RSZ;
        int rem = idx - ki * RSZ;
        int cl = rem / Ww;
        int j  = rem - cl * Ww;
        int ii = i + ki - 1;
        float v = 0.f;
        if (ii >= 0 && ii < Hh)
            v = x[(size_t)(b * Cch + q * CQ + cl) * (Hh * Ww) + ii * Ww + j];
        xs[idx] = v;
    }
    __syncthreads();

    const int dg = q * 576 + tid;
    const int c  = dg / 9;
    const int r  = dg - c * 9;
    const int ki = r / 3;
    const int kj = r - ki * 3;
    const int soff = ki * RSZ + (c - q * CQ) * Ww;

    for (int j = 0; j < Ww; j++) {
        int jj = j + kj - 1;
        float v = (jj >= 0 && jj < Ww) ? xs[soff + jj] : 0.f;
        size_t o = ((size_t)(b * Hh + i) * Ww + j) * Dd + dg;
        g_t16[o] = __float2half(v);
    }
}

// ---------------------------------------------------------------------------
// HMMA GEMM: C[M=25088, N] = act(A[M,K] @ B^T + bias)
//   A, B single fp16 (A row-major [M][K], B K-major [N][K]); fp32 acc.
// Tile BM=128 x BN=128 x BK=32, 256 threads (8 warps 4m x 2n, warp 32x64),
// 80B-padded smem rows (conflict-free ldmatrix), cp.async double buffer.
// EPI: 0 relu->g_h116, 1 t*sigmoid->g_t16 in place, 2 bias->Cout fp32
// ---------------------------------------------------------------------------
template<int KD, int EPI>
__global__ __launch_bounds__(256, 2) void gemm_mma(
    const __half* __restrict__ A_g,
    const __half* __restrict__ B_g,
    const float* __restrict__ bias,
    float* __restrict__ Cout)
{
    constexpr int BM = 128, BN = 128, BK = 32;
    constexpr int NT = KD / BK;
    constexpr int NOUT = (EPI == 1) ? Dd : Cch;
    constexpr unsigned ROWB = 80;                 // padded smem row bytes
    constexpr unsigned MATB = 128 * ROWB;         // 10240
    constexpr unsigned OFF_A = 0, OFF_B = MATB;
    constexpr unsigned STAGE = 2 * MATB;          // 20480
    constexpr unsigned OFF_BIAS = 2 * STAGE;      // 40960

    extern __shared__ char smem[];
    const unsigned sb = smem_u32(smem);
    float* sm_bias = (float*)(smem + OFF_BIAS);

    const int tid = threadIdx.x;
    const int wid = tid >> 5;
    const int lid = tid & 31;
    const int wm  = wid & 3;
    const int wn  = wid >> 2;
    const int bm  = blockIdx.y * BM;
    const int bn  = blockIdx.x * BN;

    const int srow  = tid >> 1;
    const int shalf = tid & 1;
    const unsigned sts_off = (unsigned)srow * ROWB + (unsigned)shalf * 32;

    const unsigned a_lane = (unsigned)((((lid >> 3) & 1) * 8 + (lid & 7))) * ROWB
                          + (unsigned)(lid >> 4) * 16;
    const unsigned b_lane = (unsigned)((((lid >> 4) & 1) * 8 + (lid & 7))) * ROWB
                          + (unsigned)((lid >> 3) & 1) * 16;

    if (tid < BN) sm_bias[tid] = bias[bn + tid];

    // per-thread global source bases (advance by BK per tile)
    const __half* pA = A_g + (size_t)(bm + srow) * KD + shalf * 16;
    const __half* pB = B_g + (size_t)(bn + srow) * KD + shalf * 16;

    float acc[2][8][4];
    #pragma unroll
    for (int i = 0; i < 2; i++)
        #pragma unroll
        for (int j = 0; j < 8; j++)
            #pragma unroll
            for (int v = 0; v < 4; v++)
                acc[i][j][v] = 0.f;

    // prologue: stage tile 0 into buffer 0
    {
        unsigned d = sb + sts_off;
        CP_ASYNC16(d + OFF_A,      pA);
        CP_ASYNC16(d + OFF_A + 16, pA + 8);
        CP_ASYNC16(d + OFF_B,      pB);
        CP_ASYNC16(d + OFF_B + 16, pB + 8);
        CP_COMMIT();
    }
    CP_WAIT0();
    __syncthreads();

    for (int t = 0; t < NT; t++) {
        const unsigned so = (t & 1) ? STAGE : 0;
        const bool has_next = (t + 1 < NT);

        if (has_next) {
            const int k0 = (t + 1) * BK;
            unsigned d = sb + ((t & 1) ? 0u : STAGE) + sts_off;
            CP_ASYNC16(d + OFF_A,      pA + k0);
            CP_ASYNC16(d + OFF_A + 16, pA + k0 + 8);
            CP_ASYNC16(d + OFF_B,      pB + k0);
            CP_ASYNC16(d + OFF_B + 16, pB + k0 + 8);
            CP_COMMIT();
        }

        #pragma unroll
        for (int ks = 0; ks < 2; ks++) {
            const unsigned kso = (unsigned)ks * 32;
            unsigned Af[2][4];
            #pragma unroll
            for (int i = 0; i < 2; i++) {
                unsigned arow = (unsigned)(wm * 32 + i * 16) * ROWB + kso;
                ldsm4(sb + so + OFF_A + arow + a_lane, Af[i]);
            }
            unsigned Bf[4][4];
            #pragma unroll
            for (int g = 0; g < 4; g++) {
                unsigned brow = (unsigned)(wn * 64 + g * 16) * ROWB + kso;
                ldsm4(sb + so + OFF_B + brow + b_lane, Bf[g]);
            }
            #pragma unroll
            for (int i = 0; i < 2; i++)
                #pragma unroll
                for (int g = 0; g < 4; g++) {
                    mma16816(acc[i][2 * g],     Af[i], Bf[g][0], Bf[g][1]);
                    mma16816(acc[i][2 * g + 1], Af[i], Bf[g][2], Bf[g][3]);
                }
        }

        if (has_next) {
            CP_WAIT0();
            __syncthreads();
        }
    }

    // ---- epilogue ----
    const int g  = lid >> 2;
    const int tt = lid & 3;
    #pragma unroll
    for (int i = 0; i < 2; i++) {
        const int row0 = bm + wm * 32 + i * 16 + g;
        #pragma unroll
        for (int j = 0; j < 8; j++) {
            const int coll = wn * 64 + j * 8 + tt * 2;
            const int col  = bn + coll;
            const float b0 = sm_bias[coll];
            const float b1 = sm_bias[coll + 1];
            #pragma unroll
            for (int half = 0; half < 2; half++) {
                const int row = row0 + half * 8;
                float v0 = acc[i][j][2 * half + 0] + b0;
                float v1 = acc[i][j][2 * half + 1] + b1;
                if (EPI == 0) {
                    __half2 h = __floats2half2_rn(fmaxf(v0, 0.f), fmaxf(v1, 0.f));
                    *(__half2*)&g_h116[(size_t)row * NOUT + col] = h;
                } else if (EPI == 2) {
                    float2 v = make_float2(v0, v1);
                    *(float2*)&Cout[(size_t)row * NOUT + col] = v;
                } else {
                    size_t o = (size_t)row * NOUT + col;
                    __half2 tp = *(__half2*)&g_t16[o];
                    float t0 = __half2float(__low2half(tp));
                    float t1 = __half2float(__high2half(tp));
                    float ts0 = t0 * __fdividef(1.f, 1.f + __expf(-v0));
                    float ts1 = t1 * __fdividef(1.f, 1.f + __expf(-v1));
                    *(__half2*)&g_t16[o] = __floats2half2_rn(ts0, ts1);
                }
            }
        }
    }
}

// ---------------------------------------------------------------------------
// Launch
// ---------------------------------------------------------------------------
extern "C" void kernel_launch(void* const* d_in, const int* in_sizes, int n_in,
                              void* d_out, int out_size)
{
    const float* x  = (const float*)d_in[0];
    const float* W1 = (const float*)d_in[1];
    const float* b1 = (const float*)d_in[2];
    const float* W2 = (const float*)d_in[3];
    const float* b2 = (const float*)d_in[4];
    const float* W3 = (const float*)d_in[5];
    const float* b3 = (const float*)d_in[6];
    float* out = (float*)d_out;
    (void)in_sizes; (void)n_in; (void)out_size;

    const int SM_GEMM = 2 * 20480 + 512;   // 41472
    cudaFuncSetAttribute(gemm_mma<Dd,  0>, cudaFuncAttributeMaxDynamicSharedMemorySize, SM_GEMM);
    cudaFuncSetAttribute(gemm_mma<Cch, 1>, cudaFuncAttributeMaxDynamicSharedMemorySize, SM_GEMM);
    cudaFuncSetAttribute(gemm_mma<Dd,  2>, cudaFuncAttributeMaxDynamicSharedMemorySize, SM_GEMM);

    __half *w1, *w2, *w3, *t16, *h116;
    cudaGetSymbolAddress((void**)&w1,  g_W1T);
    cudaGetSymbolAddress((void**)&w2,  g_W2T);
    cudaGetSymbolAddress((void**)&w3,  g_W3T);
    cudaGetSymbolAddress((void**)&t16,  g_t16);
    cudaGetSymbolAddress((void**)&h116, g_h116);

    // weight transpose -> fp16
    transpose_w<<<dim3(Cch / 32, Dd / 32), dim3(32, 8)>>>(W1, w1, Dd, Cch);
    transpose_w<<<dim3(Dd / 32, Cch / 32), dim3(32, 8)>>>(W2, w2, Cch, Dd);
    transpose_w<<<dim3(Cch / 32, Dd / 32), dim3(32, 8)>>>(W3, w3, Dd, Cch);

    // unfold: x -> g_t16 (row-major [L][2304], single fp16)
    unfold_kernel<<<dim3(Bsz * Hh, 4), 576>>>(x);

    // GEMM1: h1 = relu(t @ W1 + b1)        M=25088, N=256,  K=2304
    gemm_mma<Dd, 0><<<dim3(Cch / 128, Lrows / 128), 256, SM_GEMM>>>(
        t16, w1, b1, nullptr);

    // GEMM2: t = t * sigmoid(h1 @ W2 + b2) M=25088, N=2304, K=256
    gemm_mma<Cch, 1><<<dim3(Dd / 128, Lrows / 128), 256, SM_GEMM>>>(
        h116, w2, b2, nullptr);

    // GEMM3: out = ts @ W3 + b3            M=25088, N=256,  K=2304
    gemm_mma<Dd, 2><<<dim3(Cch / 128, Lrows / 128), 256, SM_GEMM>>>(
        t16, w3, b3, out);
}